// round 10
// baseline (speedup 1.0000x reference)
#include <cuda_runtime.h>
#include <cuda_bf16.h>
#include <cstdint>

#define B_  4
#define S_  2048
#define D_  768
#define H_  12
#define M_  (B_ * S_)     // 8192
#define NF_ (3 * D_)      // 2304 fused qkv cols

// ------------------------- device scratch (no allocs) -----------------------
__device__ __nv_bfloat16  g_xh [(size_t)M_ * D_];    // residual hi/lo
__device__ __nv_bfloat16  g_xl [(size_t)M_ * D_];
__device__ __nv_bfloat16  g_qh [(size_t)M_ * D_];    // q (pre-scaled) hi/lo
__device__ __nv_bfloat16  g_ql [(size_t)M_ * D_];
__device__ __nv_bfloat16  g_kh [(size_t)M_ * D_];    // k hi/lo
__device__ __nv_bfloat16  g_kl [(size_t)M_ * D_];
__device__ __nv_bfloat16  g_vth[(size_t)B_ * H_ * 64 * S_];  // v^T [bh][dh][s]
__device__ __nv_bfloat16  g_vtl[(size_t)B_ * H_ * 64 * S_];
__device__ __nv_bfloat16  g_zh [(size_t)M_ * D_];    // attention out hi/lo
__device__ __nv_bfloat16  g_zl [(size_t)M_ * D_];
__device__ __nv_bfloat16  g_wth[(size_t)NF_ * D_];   // W_{q,k,v}^T  [n][d]
__device__ __nv_bfloat16  g_wtl[(size_t)NF_ * D_];
__device__ __nv_bfloat16  g_woh[(size_t)D_ * D_];    // W_O^T [d_out][he]
__device__ __nv_bfloat16  g_wol[(size_t)D_ * D_];
__device__ float          g_fb [NF_];                // fused qkv bias

// ------------------------------ PTX helpers --------------------------------
__device__ __forceinline__ uint32_t smem_u32(const void* p) {
    uint32_t a;
    asm("{ .reg .u64 t; cvta.to.shared.u64 t, %1; cvt.u32.u64 %0, t; }"
        : "=r"(a) : "l"(p));
    return a;
}
__device__ __forceinline__ void ldsm_x4(uint32_t* r, uint32_t addr) {
    asm volatile("ldmatrix.sync.aligned.m8n8.x4.shared.b16 {%0,%1,%2,%3}, [%4];"
                 : "=r"(r[0]), "=r"(r[1]), "=r"(r[2]), "=r"(r[3]) : "r"(addr));
}
__device__ __forceinline__ void mma16816(float* c, const uint32_t* a,
                                         uint32_t b0, uint32_t b1) {
    asm volatile(
        "mma.sync.aligned.m16n8k16.row.col.f32.bf16.bf16.f32 "
        "{%0,%1,%2,%3}, {%4,%5,%6,%7}, {%8,%9}, {%0,%1,%2,%3};"
        : "+f"(c[0]), "+f"(c[1]), "+f"(c[2]), "+f"(c[3])
        : "r"(a[0]), "r"(a[1]), "r"(a[2]), "r"(a[3]), "r"(b0), "r"(b1));
}
__device__ __forceinline__ void split2(float a, float b, uint32_t& hi, uint32_t& lo) {
    __nv_bfloat16 ha = __float2bfloat16(a), hb = __float2bfloat16(b);
    __nv_bfloat16 la = __float2bfloat16(a - __bfloat162float(ha));
    __nv_bfloat16 lb = __float2bfloat16(b - __bfloat162float(hb));
    __nv_bfloat162 hp = {ha, hb}, lp = {la, lb};
    hi = *(uint32_t*)&hp; lo = *(uint32_t*)&lp;
}
__device__ __forceinline__ void split1(float v, __nv_bfloat16& h, __nv_bfloat16& l) {
    h = __float2bfloat16(v);
    l = __float2bfloat16(v - __bfloat162float(h));
}
#define CP_ASYNC16(dst, src) \
    asm volatile("cp.async.cg.shared.global [%0], [%1], 16;" :: "r"(dst), "l"(src))
#define CP_COMMIT() asm volatile("cp.async.commit_group;" ::: "memory")
#define CP_WAIT(n)  asm volatile("cp.async.wait_group %0;" :: "n"(n) : "memory")

// --------------------------- conversion kernels ----------------------------
__global__ void split_kernel(const float* __restrict__ src,
                             __nv_bfloat16* __restrict__ dh,
                             __nv_bfloat16* __restrict__ dl, int n) {
    int i8 = (blockIdx.x * 256 + threadIdx.x) * 8;
    if (i8 >= n) return;
    float4 v0 = *(const float4*)&src[i8];
    float4 v1 = *(const float4*)&src[i8 + 4];
    float v[8] = {v0.x, v0.y, v0.z, v0.w, v1.x, v1.y, v1.z, v1.w};
    __align__(16) __nv_bfloat16 h[8], l[8];
#pragma unroll
    for (int j = 0; j < 8; j++) {
        h[j] = __float2bfloat16(v[j]);
        l[j] = __float2bfloat16(v[j] - __bfloat162float(h[j]));
    }
    *(uint4*)&dh[i8] = *(uint4*)h;
    *(uint4*)&dl[i8] = *(uint4*)l;
}

__device__ __forceinline__ void trans_tile(const float* src, int src_ld,
                                           __nv_bfloat16* dh, __nv_bfloat16* dl,
                                           int dst_ld, int r0, int c0, int base) {
    __shared__ float ts[64 * 65];
    const int tid = threadIdx.x;
#pragma unroll
    for (int it = 0; it < 16; it++) {
        int flat = tid + it * 256;
        int i = flat >> 6, c = flat & 63;
        ts[c * 65 + i] = src[(size_t)(r0 + i) * src_ld + c0 + c];
    }
    __syncthreads();
#pragma unroll
    for (int it = 0; it < 8; it++) {
        int flat = tid + it * 256;
        int c = flat >> 5, rj = flat & 31;
        uint32_t hp, lp;
        split2(ts[c * 65 + rj * 2], ts[c * 65 + rj * 2 + 1], hp, lp);
        size_t o = (size_t)(base + c0 + c) * dst_ld + r0 + rj * 2;
        *(uint32_t*)&dh[o] = hp;
        *(uint32_t*)&dl[o] = lp;
    }
}

__global__ void trans_qkv_kernel(const float* __restrict__ Wq,
                                 const float* __restrict__ Wk,
                                 const float* __restrict__ Wv,
                                 const float* __restrict__ bq,
                                 const float* __restrict__ bk,
                                 const float* __restrict__ bv) {
    const int by = blockIdx.y;
    const int t = by / H_, h = by % H_;
    if (blockIdx.x == 0 && threadIdx.x < 64) {
        const float* bp = (t == 0) ? bq : (t == 1) ? bk : bv;
        g_fb[t * D_ + h * 64 + threadIdx.x] = bp[h * 64 + threadIdx.x];
    }
    const float* src = ((t == 0) ? Wq : (t == 1) ? Wk : Wv) + (size_t)h * D_ * 64;
    trans_tile(src, 64, g_wth, g_wtl, D_, blockIdx.x * 64, 0, t * D_ + h * 64);
}
__global__ void trans_wo_kernel(const float* __restrict__ Wo) {
    trans_tile(Wo, D_, g_woh, g_wol, D_, blockIdx.x * 64, blockIdx.y * 64, 0);
}

// ------------------------ mma.sync bf16x3 GEMM ------------------------------
// Occupancy 1, uncapped regs, 3-stage cp.async pipeline (depth-2 prefetch).
// BK=32, CTA 128x128, 8 warps (2x4). MODE 1 writes q/k split bf16 and V
// TRANSPOSED split bf16 (fusing the old trans_v kernel).
#define GP_   5120                 // elements per part (128*40)
#define GSTG_ (4 * GP_)            // elements per stage
#define NSTG_ 3
template <int MODE>
__global__ __launch_bounds__(256, 1)
void gemm_mma_kernel(const __nv_bfloat16* __restrict__ Ah,
                     const __nv_bfloat16* __restrict__ Al,
                     const __nv_bfloat16* __restrict__ Bh,
                     const __nv_bfloat16* __restrict__ Bl,
                     float* __restrict__ out, int ld_out,
                     const float* __restrict__ bias) {
    extern __shared__ __align__(16) char gsm[];
    const uint32_t sb = smem_u32(gsm);

    const int tid  = threadIdx.x;
    const int wid  = tid >> 5;
    const int lane = tid & 31;
    const int wr   = wid >> 2;
    const int wc   = wid & 3;
    const size_t m0 = blockIdx.y * 128;
    const size_t n0 = blockIdx.x * 128;

    const __nv_bfloat16* srcs[4] = {Ah, Al, Bh, Bl};
    const size_t rbase[4] = {m0, m0, n0, n0};

    auto load_st = [&](int kt, int st) {
        const int k0 = kt * 32;
#pragma unroll
        for (int it = 0; it < 8; it++) {
            int idx = tid + it * 256;
            int part = idx >> 9;
            int w = idx & 511;
            int row = w >> 2, c8 = w & 3;
            uint32_t dst = sb + (st * GSTG_ + part * GP_ + row * 40 + c8 * 8) * 2;
            const __nv_bfloat16* src =
                &srcs[part][(rbase[part] + row) * D_ + k0 + c8 * 8];
            CP_ASYNC16(dst, src);
        }
        CP_COMMIT();
    };

    float acc[4][4][4] = {};

    const int lrow = lane & 15;
    const int lcol = (lane >> 4) * 8;

    load_st(0, 0);
    load_st(1, 1);

    int st = 0;
    for (int kt = 0; kt < 24; kt++) {
        if (kt + 2 < 24) { load_st(kt + 2, (kt + 2) % NSTG_); CP_WAIT(2); }
        else if (kt + 2 == 24) { CP_WAIT(1); }
        else { CP_WAIT(0); }
        __syncthreads();

        const uint32_t s0 = sb + (st * GSTG_) * 2;
#pragma unroll
        for (int ks = 0; ks < 2; ks++) {
            const int kb = ks * 16;
            const uint32_t arow = s0 + ((wr * 64 + lrow) * 40 + kb + lcol) * 2;
            const uint32_t brow = s0 + ((wc * 32 + lrow) * 40 + kb + lcol) * 2;

            uint32_t aFh[4][4], aFl[4][4], bFh[2][4], bFl[2][4];
#pragma unroll
            for (int mt = 0; mt < 4; mt++) {
                ldsm_x4(aFh[mt], arow + (0 * GP_ + mt * 16 * 40) * 2);
                ldsm_x4(aFl[mt], arow + (1 * GP_ + mt * 16 * 40) * 2);
            }
#pragma unroll
            for (int np = 0; np < 2; np++) {
                ldsm_x4(bFh[np], brow + (2 * GP_ + np * 16 * 40) * 2);
                ldsm_x4(bFl[np], brow + (3 * GP_ + np * 16 * 40) * 2);
            }
#pragma unroll
            for (int mt = 0; mt < 4; mt++)
#pragma unroll
                for (int nt = 0; nt < 4; nt++) {
                    const int np = nt >> 1, ni = nt & 1;
                    mma16816(acc[mt][nt], aFh[mt], bFh[np][ni], bFh[np][ni + 2]);
                    mma16816(acc[mt][nt], aFh[mt], bFl[np][ni], bFl[np][ni + 2]);
                    mma16816(acc[mt][nt], aFl[mt], bFh[np][ni], bFh[np][ni + 2]);
                }
        }
        __syncthreads();
        st = (st + 1 == NSTG_) ? 0 : st + 1;
    }

    const int g = lane >> 2;
    const int cb = (lane & 3) * 2;

    if (MODE == 0) {
#pragma unroll
        for (int mt = 0; mt < 4; mt++)
#pragma unroll
            for (int nt = 0; nt < 4; nt++) {
                const size_t col = n0 + wc * 32 + nt * 8 + cb;
                float2 bv = *(const float2*)&bias[col];
                const size_t r0 = m0 + wr * 64 + mt * 16 + g;
                float2 v0 = {acc[mt][nt][0] + bv.x, acc[mt][nt][1] + bv.y};
                float2 v1 = {acc[mt][nt][2] + bv.x, acc[mt][nt][3] + bv.y};
                *(float2*)&out[r0 * ld_out + col]       = v0;
                *(float2*)&out[(r0 + 8) * ld_out + col] = v1;
            }
    } else {
        const int t  = (int)(n0 / D_);
        const int nn = (int)(n0 - t * D_);
        if (t < 2) {
            __nv_bfloat16* dh = (t == 0) ? g_qh : g_kh;
            __nv_bfloat16* dl = (t == 0) ? g_ql : g_kl;
            const float sc = (t == 0) ? 0.125f : 1.0f;
#pragma unroll
            for (int mt = 0; mt < 4; mt++)
#pragma unroll
                for (int nt = 0; nt < 4; nt++) {
                    const int colw = nn + wc * 32 + nt * 8 + cb;
                    float2 bv = *(const float2*)&bias[n0 + wc * 32 + nt * 8 + cb];
                    const size_t r0 = m0 + wr * 64 + mt * 16 + g;
                    uint32_t h0, l0, h1, l1;
                    split2((acc[mt][nt][0] + bv.x) * sc, (acc[mt][nt][1] + bv.y) * sc, h0, l0);
                    split2((acc[mt][nt][2] + bv.x) * sc, (acc[mt][nt][3] + bv.y) * sc, h1, l1);
                    *(uint32_t*)&dh[r0 * D_ + colw]       = h0;
                    *(uint32_t*)&dl[r0 * D_ + colw]       = l0;
                    *(uint32_t*)&dh[(r0 + 8) * D_ + colw] = h1;
                    *(uint32_t*)&dl[(r0 + 8) * D_ + colw] = l1;
                }
        } else {
            // V: write transposed split directly: vth[(b*H+h)*64+e][s]
            const int bidx = (int)(m0 / S_);
#pragma unroll
            for (int mt = 0; mt < 4; mt++)
#pragma unroll
                for (int nt = 0; nt < 4; nt++) {
                    const int colw = nn + wc * 32 + nt * 8 + cb;   // h*64+e
                    const int hh = colw >> 6, e = colw & 63;
                    float2 bv = *(const float2*)&bias[n0 + wc * 32 + nt * 8 + cb];
                    const size_t r0 = m0 + wr * 64 + mt * 16 + g;
                    const int s = (int)(r0 - (size_t)bidx * S_);
                    const size_t ob = ((size_t)(bidx * H_ + hh) * 64 + e) * S_;
                    float v00 = acc[mt][nt][0] + bv.x;   // (s,   e)
                    float v01 = acc[mt][nt][1] + bv.y;   // (s,   e+1)
                    float v10 = acc[mt][nt][2] + bv.x;   // (s+8, e)
                    float v11 = acc[mt][nt][3] + bv.y;   // (s+8, e+1)
                    __nv_bfloat16 hh0, ll0;
                    split1(v00, hh0, ll0); g_vth[ob + s] = hh0;          g_vtl[ob + s] = ll0;
                    split1(v01, hh0, ll0); g_vth[ob + S_ + s] = hh0;     g_vtl[ob + S_ + s] = ll0;
                    split1(v10, hh0, ll0); g_vth[ob + s + 8] = hh0;      g_vtl[ob + s + 8] = ll0;
                    split1(v11, hh0, ll0); g_vth[ob + S_ + s + 8] = hh0; g_vtl[ob + S_ + s + 8] = ll0;
                }
        }
    }
}

// ------------------- mma.sync bf16x3 causal flash attention (R8) ------------
#define PART_ 4608                 // elements per part (64*72)
#define BUF_  (4 * PART_)          // elements per KV buffer
__global__ __launch_bounds__(256, 1) void attn_mma_kernel() {
    extern __shared__ __align__(16) char dsm[];
    __nv_bfloat16* sm = (__nv_bfloat16*)dsm;
    const uint32_t sb = smem_u32(sm);

    const int tid = threadIdx.x, wid = tid >> 5, lane = tid & 31;
    const int qt = gridDim.x - 1 - blockIdx.x;
    const int bh = blockIdx.y;
    const int b = bh / H_, h = bh % H_;
    const int q0 = qt * 128;

#pragma unroll
    for (int it = 0; it < 8; it++) {
        int idx = tid + it * 256;
        int part = idx >> 10;
        int w = idx & 1023;
        int r = w >> 3, c8 = w & 7;
        const __nv_bfloat16* src = part ? g_ql : g_qh;
        *(uint4*)&sm[part * 9216 + r * 72 + c8 * 8] =
            *(const uint4*)&src[(size_t)(b * S_ + q0 + r) * D_ + h * 64 + c8 * 8];
    }
    __syncthreads();

    uint32_t aQh[4][4], aQl[4][4];
    {
        const int row = wid * 16 + (lane & 15);
        const int c8 = (lane >> 4) * 8;
#pragma unroll
        for (int kk = 0; kk < 4; kk++) {
            ldsm_x4(aQh[kk], sb + (row * 72 + kk * 16 + c8) * 2);
            ldsm_x4(aQl[kk], sb + (9216 + row * 72 + kk * 16 + c8) * 2);
        }
    }
    __syncthreads();

    float oacc[8][4] = {};
    float mrun[2] = {-1e30f, -1e30f}, lrun[2] = {0.0f, 0.0f};

    const int lrw = lane & 15;
    const int cb8 = (lane >> 4) * 8;
    const int ntiles = 2 * qt + 2;

    auto load_tile = [&](int kt, int bs) {
        const int k0 = kt * 64;
#pragma unroll
        for (int it = 0; it < 8; it++) {
            int idx = tid + it * 256;
            int part = idx >> 9;
            int w = idx & 511;
            int row = w >> 3, c8 = w & 7;
            uint32_t dst = sb + (bs * BUF_ + part * PART_ + row * 72 + c8 * 8) * 2;
            const __nv_bfloat16* src;
            if (part < 2) {
                const __nv_bfloat16* base = part ? g_kl : g_kh;
                src = &base[(size_t)(b * S_ + k0 + row) * D_ + h * 64 + c8 * 8];
            } else {
                const __nv_bfloat16* base = (part == 2) ? g_vth : g_vtl;
                src = &base[((size_t)bh * 64 + row) * S_ + k0 + c8 * 8];
            }
            CP_ASYNC16(dst, src);
        }
        CP_COMMIT();
    };

    load_tile(0, 0);

    for (int kt = 0; kt < ntiles; kt++) {
        const int bs = kt & 1;
        if (kt + 1 < ntiles) { load_tile(kt + 1, 1 - bs); CP_WAIT(1); }
        else                 { CP_WAIT(0); }
        __syncthreads();

        const uint32_t kbase = sb + (bs * BUF_) * 2;
        const uint32_t vbase = sb + (bs * BUF_ + 2 * PART_) * 2;

        float sacc[8][4] = {};
#pragma unroll
        for (int kk = 0; kk < 4; kk++) {
#pragma unroll
            for (int np = 0; np < 4; np++) {
                uint32_t kbh[4], kbl[4];
                ldsm_x4(kbh, kbase + ((np * 16 + lrw) * 72 + kk * 16 + cb8) * 2);
                ldsm_x4(kbl, kbase + (PART_ + (np * 16 + lrw) * 72 + kk * 16 + cb8) * 2);
#pragma unroll
                for (int ni = 0; ni < 2; ni++) {
                    const int nt = np * 2 + ni;
                    mma16816(sacc[nt], aQh[kk], kbh[ni], kbh[ni + 2]);
                    mma16816(sacc[nt], aQh[kk], kbl[ni], kbl[ni + 2]);
                    mma16816(sacc[nt], aQl[kk], kbh[ni], kbh[ni + 2]);
                }
            }
        }

        const int k0 = kt * 64;
        if (kt >= 2 * qt) {
#pragma unroll
            for (int nt = 0; nt < 8; nt++)
#pragma unroll
                for (int e = 0; e < 4; e++) {
                    const int row = q0 + wid * 16 + (lane >> 2) + (e >> 1) * 8;
                    const int col = k0 + nt * 8 + (lane & 3) * 2 + (e & 1);
                    if (col > row) sacc[nt][e] = -1e30f;
                }
        }

#pragma unroll
        for (int rg = 0; rg < 2; rg++) {
            float mloc = -1e30f;
#pragma unroll
            for (int nt = 0; nt < 8; nt++)
                mloc = fmaxf(mloc, fmaxf(sacc[nt][rg * 2], sacc[nt][rg * 2 + 1]));
            mloc = fmaxf(mloc, __shfl_xor_sync(0xffffffffu, mloc, 1));
            mloc = fmaxf(mloc, __shfl_xor_sync(0xffffffffu, mloc, 2));
            const float mnew = fmaxf(mrun[rg], mloc);
            const float alpha = __expf(mrun[rg] - mnew);
            float lloc = 0.0f;
#pragma unroll
            for (int nt = 0; nt < 8; nt++) {
                sacc[nt][rg * 2]     = __expf(sacc[nt][rg * 2] - mnew);
                sacc[nt][rg * 2 + 1] = __expf(sacc[nt][rg * 2 + 1] - mnew);
                lloc += sacc[nt][rg * 2] + sacc[nt][rg * 2 + 1];
            }
            lloc += __shfl_xor_sync(0xffffffffu, lloc, 1);
            lloc += __shfl_xor_sync(0xffffffffu, lloc, 2);
            lrun[rg] = lrun[rg] * alpha + lloc;
            mrun[rg] = mnew;
#pragma unroll
            for (int dt = 0; dt < 8; dt++) {
                oacc[dt][rg * 2]     *= alpha;
                oacc[dt][rg * 2 + 1] *= alpha;
            }
        }

        uint32_t aPh[4][4], aPl[4][4];
#pragma unroll
        for (int k2 = 0; k2 < 4; k2++) {
            split2(sacc[k2 * 2][0],     sacc[k2 * 2][1],     aPh[k2][0], aPl[k2][0]);
            split2(sacc[k2 * 2][2],     sacc[k2 * 2][3],     aPh[k2][1], aPl[k2][1]);
            split2(sacc[k2 * 2 + 1][0], sacc[k2 * 2 + 1][1], aPh[k2][2], aPl[k2][2]);
            split2(sacc[k2 * 2 + 1][2], sacc[k2 * 2 + 1][3], aPh[k2][3], aPl[k2][3]);
        }

#pragma unroll
        for (int k2 = 0; k2 < 4; k2++) {
#pragma unroll
            for (int dp = 0; dp < 4; dp++) {
                uint32_t vbh[4], vbl[4];
                ldsm_x4(vbh, vbase + ((dp * 16 + lrw) * 72 + k2 * 16 + cb8) * 2);
                ldsm_x4(vbl, vbase + (PART_ + (dp * 16 + lrw) * 72 + k2 * 16 + cb8) * 2);
#pragma unroll
                for (int ni = 0; ni < 2; ni++) {
                    const int dt = dp * 2 + ni;
                    mma16816(oacc[dt], aPh[k2], vbh[ni], vbh[ni + 2]);
                    mma16816(oacc[dt], aPh[k2], vbl[ni], vbl[ni + 2]);
                    mma16816(oacc[dt], aPl[k2], vbh[ni], vbh[ni + 2]);
                }
            }
        }
        __syncthreads();
    }

#pragma unroll
    for (int rg = 0; rg < 2; rg++) {
        const float inv = 1.0f / lrun[rg];
        const int row = q0 + wid * 16 + (lane >> 2) + rg * 8;
#pragma unroll
        for (int dt = 0; dt < 8; dt++) {
            const size_t o = (size_t)(b * S_ + row) * D_ + h * 64 + dt * 8 + (lane & 3) * 2;
            uint32_t hp, lp;
            split2(oacc[dt][rg * 2] * inv, oacc[dt][rg * 2 + 1] * inv, hp, lp);
            *(uint32_t*)&g_zh[o] = hp;
            *(uint32_t*)&g_zl[o] = lp;
        }
    }
}

// --------------------------------- launch ----------------------------------
extern "C" void kernel_launch(void* const* d_in, const int* in_sizes, int n_in,
                              void* d_out, int out_size) {
    const float* X  = (const float*)d_in[0];
    const float* Wq = (const float*)d_in[1];
    const float* Wk = (const float*)d_in[2];
    const float* Wv = (const float*)d_in[3];
    const float* Wo = (const float*)d_in[4];
    const float* bq = (const float*)d_in[5];
    const float* bk = (const float*)d_in[6];
    const float* bv = (const float*)d_in[7];
    const float* bo = (const float*)d_in[8];
    float* out = (float*)d_out;

    const int attn_smem = 2 * BUF_ * 2;          // 73728 B
    const int gemm_smem = NSTG_ * GSTG_ * 2;     // 122880 B
    static bool attr_set = false;
    if (!attr_set) {
        cudaFuncSetAttribute(attn_mma_kernel,
                             cudaFuncAttributeMaxDynamicSharedMemorySize, attn_smem);
        cudaFuncSetAttribute(gemm_mma_kernel<0>,
                             cudaFuncAttributeMaxDynamicSharedMemorySize, gemm_smem);
        cudaFuncSetAttribute(gemm_mma_kernel<1>,
                             cudaFuncAttributeMaxDynamicSharedMemorySize, gemm_smem);
        attr_set = true;
    }

    static __nv_bfloat16 *xh = nullptr, *xl, *zh, *zl, *wth, *wtl, *woh, *wol;
    static float *fb;
    if (!xh) {
        cudaGetSymbolAddress((void**)&xh,  g_xh);
        cudaGetSymbolAddress((void**)&xl,  g_xl);
        cudaGetSymbolAddress((void**)&zh,  g_zh);
        cudaGetSymbolAddress((void**)&zl,  g_zl);
        cudaGetSymbolAddress((void**)&wth, g_wth);
        cudaGetSymbolAddress((void**)&wtl, g_wtl);
        cudaGetSymbolAddress((void**)&woh, g_woh);
        cudaGetSymbolAddress((void**)&wol, g_wol);
        cudaGetSymbolAddress((void**)&fb,  g_fb);
    }

    // 1) conversions
    split_kernel<<<(M_ * D_) / (256 * 8), 256>>>(X, xh, xl, M_ * D_);
    trans_qkv_kernel<<<dim3(D_ / 64, 3 * H_), 256>>>(Wq, Wk, Wv, bq, bk, bv);
    trans_wo_kernel<<<dim3(D_ / 64, D_ / 64), 256>>>(Wo);

    // 2) fused QKV projection -> split bf16 q/k (natural) + v (transposed)
    gemm_mma_kernel<1><<<dim3(NF_ / 128, M_ / 128), 256, gemm_smem>>>(
        xh, xl, wth, wtl, nullptr, 0, fb);

    // 3) causal attention (tensor cores)
    attn_mma_kernel<<<dim3(S_ / 128, B_ * H_), 256, attn_smem>>>();

    // 4) output projection
    gemm_mma_kernel<0><<<dim3(D_ / 128, M_ / 128), 256, gemm_smem>>>(
        zh, zl, woh, wol, out, D_, bo);
}

// round 11
// speedup vs baseline: 1.0071x; 1.0071x over previous
#include <cuda_runtime.h>
#include <cuda_bf16.h>
#include <cstdint>

#define B_  4
#define S_  2048
#define D_  768
#define H_  12
#define M_  (B_ * S_)     // 8192
#define NF_ (3 * D_)      // 2304 fused qkv cols

// ------------------------- device scratch (no allocs) -----------------------
__device__ __nv_bfloat16  g_xh [(size_t)M_ * D_];    // residual hi/lo
__device__ __nv_bfloat16  g_xl [(size_t)M_ * D_];
__device__ __nv_bfloat16  g_qh [(size_t)M_ * D_];    // q (pre-scaled) hi/lo
__device__ __nv_bfloat16  g_ql [(size_t)M_ * D_];
__device__ __nv_bfloat16  g_kh [(size_t)M_ * D_];    // k hi/lo
__device__ __nv_bfloat16  g_kl [(size_t)M_ * D_];
__device__ __nv_bfloat16  g_vth[(size_t)B_ * H_ * 64 * S_];  // v^T [bh][dh][s]
__device__ __nv_bfloat16  g_vtl[(size_t)B_ * H_ * 64 * S_];
__device__ __nv_bfloat16  g_zh [(size_t)M_ * D_];    // attention out hi/lo
__device__ __nv_bfloat16  g_zl [(size_t)M_ * D_];
__device__ __nv_bfloat16  g_wth[(size_t)NF_ * D_];   // W_{q,k,v}^T  [n][d]
__device__ __nv_bfloat16  g_wtl[(size_t)NF_ * D_];
__device__ __nv_bfloat16  g_woh[(size_t)D_ * D_];    // W_O^T [d_out][he]
__device__ __nv_bfloat16  g_wol[(size_t)D_ * D_];
__device__ float          g_fb [NF_];                // fused qkv bias

// ------------------------------ PTX helpers --------------------------------
__device__ __forceinline__ uint32_t smem_u32(const void* p) {
    uint32_t a;
    asm("{ .reg .u64 t; cvta.to.shared.u64 t, %1; cvt.u32.u64 %0, t; }"
        : "=r"(a) : "l"(p));
    return a;
}
__device__ __forceinline__ void ldsm_x4(uint32_t* r, uint32_t addr) {
    asm volatile("ldmatrix.sync.aligned.m8n8.x4.shared.b16 {%0,%1,%2,%3}, [%4];"
                 : "=r"(r[0]), "=r"(r[1]), "=r"(r[2]), "=r"(r[3]) : "r"(addr));
}
__device__ __forceinline__ void mma16816(float* c, const uint32_t* a,
                                         uint32_t b0, uint32_t b1) {
    asm volatile(
        "mma.sync.aligned.m16n8k16.row.col.f32.bf16.bf16.f32 "
        "{%0,%1,%2,%3}, {%4,%5,%6,%7}, {%8,%9}, {%0,%1,%2,%3};"
        : "+f"(c[0]), "+f"(c[1]), "+f"(c[2]), "+f"(c[3])
        : "r"(a[0]), "r"(a[1]), "r"(a[2]), "r"(a[3]), "r"(b0), "r"(b1));
}
__device__ __forceinline__ void split2(float a, float b, uint32_t& hi, uint32_t& lo) {
    __nv_bfloat16 ha = __float2bfloat16(a), hb = __float2bfloat16(b);
    __nv_bfloat16 la = __float2bfloat16(a - __bfloat162float(ha));
    __nv_bfloat16 lb = __float2bfloat16(b - __bfloat162float(hb));
    __nv_bfloat162 hp = {ha, hb}, lp = {la, lb};
    hi = *(uint32_t*)&hp; lo = *(uint32_t*)&lp;
}
__device__ __forceinline__ void split1(float v, __nv_bfloat16& h, __nv_bfloat16& l) {
    h = __float2bfloat16(v);
    l = __float2bfloat16(v - __bfloat162float(h));
}
#define CP_ASYNC16(dst, src) \
    asm volatile("cp.async.cg.shared.global [%0], [%1], 16;" :: "r"(dst), "l"(src))
#define CP_COMMIT() asm volatile("cp.async.commit_group;" ::: "memory")
#define CP_WAIT(n)  asm volatile("cp.async.wait_group %0;" :: "n"(n) : "memory")

// --------------------------- conversion kernels ----------------------------
__global__ void split_kernel(const float* __restrict__ src,
                             __nv_bfloat16* __restrict__ dh,
                             __nv_bfloat16* __restrict__ dl, int n) {
    int i8 = (blockIdx.x * 256 + threadIdx.x) * 8;
    if (i8 >= n) return;
    float4 v0 = *(const float4*)&src[i8];
    float4 v1 = *(const float4*)&src[i8 + 4];
    float v[8] = {v0.x, v0.y, v0.z, v0.w, v1.x, v1.y, v1.z, v1.w};
    __align__(16) __nv_bfloat16 h[8], l[8];
#pragma unroll
    for (int j = 0; j < 8; j++) {
        h[j] = __float2bfloat16(v[j]);
        l[j] = __float2bfloat16(v[j] - __bfloat162float(h[j]));
    }
    *(uint4*)&dh[i8] = *(uint4*)h;
    *(uint4*)&dl[i8] = *(uint4*)l;
}

__device__ __forceinline__ void trans_tile(const float* src, int src_ld,
                                           __nv_bfloat16* dh, __nv_bfloat16* dl,
                                           int dst_ld, int r0, int c0, int base) {
    __shared__ float ts[64 * 65];
    const int tid = threadIdx.x;
#pragma unroll
    for (int it = 0; it < 16; it++) {
        int flat = tid + it * 256;
        int i = flat >> 6, c = flat & 63;
        ts[c * 65 + i] = src[(size_t)(r0 + i) * src_ld + c0 + c];
    }
    __syncthreads();
#pragma unroll
    for (int it = 0; it < 8; it++) {
        int flat = tid + it * 256;
        int c = flat >> 5, rj = flat & 31;
        uint32_t hp, lp;
        split2(ts[c * 65 + rj * 2], ts[c * 65 + rj * 2 + 1], hp, lp);
        size_t o = (size_t)(base + c0 + c) * dst_ld + r0 + rj * 2;
        *(uint32_t*)&dh[o] = hp;
        *(uint32_t*)&dl[o] = lp;
    }
}

__global__ void trans_qkv_kernel(const float* __restrict__ Wq,
                                 const float* __restrict__ Wk,
                                 const float* __restrict__ Wv,
                                 const float* __restrict__ bq,
                                 const float* __restrict__ bk,
                                 const float* __restrict__ bv) {
    const int by = blockIdx.y;
    const int t = by / H_, h = by % H_;
    if (blockIdx.x == 0 && threadIdx.x < 64) {
        const float* bp = (t == 0) ? bq : (t == 1) ? bk : bv;
        g_fb[t * D_ + h * 64 + threadIdx.x] = bp[h * 64 + threadIdx.x];
    }
    const float* src = ((t == 0) ? Wq : (t == 1) ? Wk : Wv) + (size_t)h * D_ * 64;
    trans_tile(src, 64, g_wth, g_wtl, D_, blockIdx.x * 64, 0, t * D_ + h * 64);
}
__global__ void trans_wo_kernel(const float* __restrict__ Wo) {
    trans_tile(Wo, D_, g_woh, g_wol, D_, blockIdx.x * 64, blockIdx.y * 64, 0);
}

// ------------------------ mma.sync bf16x3 GEMM ------------------------------
// cp.async double-buffered, occ 2 (proven best). BK=32, CTA 128x128, 8 warps.
// MODE 0: fp32 out + bias. MODE 1: split bf16 q/k natural; V transposed via
// smem-staged coalesced epilogue (fuses old trans_v kernel).
#define GP_   5120                 // elements per part (128*40)
#define GSTG_ (4 * GP_)            // elements per stage
template <int MODE>
__global__ __launch_bounds__(256, 2)
void gemm_mma_kernel(const __nv_bfloat16* __restrict__ Ah,
                     const __nv_bfloat16* __restrict__ Al,
                     const __nv_bfloat16* __restrict__ Bh,
                     const __nv_bfloat16* __restrict__ Bl,
                     float* __restrict__ out, int ld_out,
                     const float* __restrict__ bias) {
    extern __shared__ __align__(16) char gsm[];
    const uint32_t sb = smem_u32(gsm);

    const int tid  = threadIdx.x;
    const int wid  = tid >> 5;
    const int lane = tid & 31;
    const int wr   = wid >> 2;
    const int wc   = wid & 3;
    const size_t m0 = blockIdx.y * 128;
    const size_t n0 = blockIdx.x * 128;

    const __nv_bfloat16* srcs[4] = {Ah, Al, Bh, Bl};
    const size_t rbase[4] = {m0, m0, n0, n0};

    auto load_st = [&](int kt, int st) {
        const int k0 = kt * 32;
#pragma unroll
        for (int it = 0; it < 8; it++) {
            int idx = tid + it * 256;
            int part = idx >> 9;
            int w = idx & 511;
            int row = w >> 2, c8 = w & 3;
            uint32_t dst = sb + (st * GSTG_ + part * GP_ + row * 40 + c8 * 8) * 2;
            const __nv_bfloat16* src =
                &srcs[part][(rbase[part] + row) * D_ + k0 + c8 * 8];
            CP_ASYNC16(dst, src);
        }
        CP_COMMIT();
    };

    float acc[4][4][4] = {};

    const int lrow = lane & 15;
    const int lcol = (lane >> 4) * 8;

    load_st(0, 0);

    for (int kt = 0; kt < 24; kt++) {
        const int st = kt & 1;
        if (kt < 23) { load_st(kt + 1, 1 - st); CP_WAIT(1); }
        else         { CP_WAIT(0); }
        __syncthreads();

        const uint32_t s0 = sb + (st * GSTG_) * 2;
#pragma unroll
        for (int ks = 0; ks < 2; ks++) {
            const int kb = ks * 16;
            const uint32_t arow = s0 + ((wr * 64 + lrow) * 40 + kb + lcol) * 2;
            const uint32_t brow = s0 + ((wc * 32 + lrow) * 40 + kb + lcol) * 2;

            uint32_t aF[4][4], bFh[2][4], bF2[2][4];
#pragma unroll
            for (int mt = 0; mt < 4; mt++)
                ldsm_x4(aF[mt], arow + (0 * GP_ + mt * 16 * 40) * 2);
#pragma unroll
            for (int np = 0; np < 2; np++)
                ldsm_x4(bFh[np], brow + (2 * GP_ + np * 16 * 40) * 2);
#pragma unroll
            for (int mt = 0; mt < 4; mt++)
#pragma unroll
                for (int nt = 0; nt < 4; nt++)
                    mma16816(acc[mt][nt], aF[mt], bFh[nt >> 1][nt & 1],
                             bFh[nt >> 1][(nt & 1) + 2]);
#pragma unroll
            for (int np = 0; np < 2; np++)
                ldsm_x4(bF2[np], brow + (3 * GP_ + np * 16 * 40) * 2);
#pragma unroll
            for (int mt = 0; mt < 4; mt++)
#pragma unroll
                for (int nt = 0; nt < 4; nt++)
                    mma16816(acc[mt][nt], aF[mt], bF2[nt >> 1][nt & 1],
                             bF2[nt >> 1][(nt & 1) + 2]);
#pragma unroll
            for (int mt = 0; mt < 4; mt++)
                ldsm_x4(aF[mt], arow + (1 * GP_ + mt * 16 * 40) * 2);
#pragma unroll
            for (int mt = 0; mt < 4; mt++)
#pragma unroll
                for (int nt = 0; nt < 4; nt++)
                    mma16816(acc[mt][nt], aF[mt], bFh[nt >> 1][nt & 1],
                             bFh[nt >> 1][(nt & 1) + 2]);
        }
        __syncthreads();
    }

    const int g = lane >> 2;
    const int cb = (lane & 3) * 2;

    if (MODE == 0) {
#pragma unroll
        for (int mt = 0; mt < 4; mt++)
#pragma unroll
            for (int nt = 0; nt < 4; nt++) {
                const size_t col = n0 + wc * 32 + nt * 8 + cb;
                float2 bv = *(const float2*)&bias[col];
                const size_t r0 = m0 + wr * 64 + mt * 16 + g;
                float2 v0 = {acc[mt][nt][0] + bv.x, acc[mt][nt][1] + bv.y};
                float2 v1 = {acc[mt][nt][2] + bv.x, acc[mt][nt][3] + bv.y};
                *(float2*)&out[r0 * ld_out + col]       = v0;
                *(float2*)&out[(r0 + 8) * ld_out + col] = v1;
            }
    } else {
        const int t  = (int)(n0 / D_);
        const int nn = (int)(n0 - t * D_);
        if (t < 2) {
            __nv_bfloat16* dh = (t == 0) ? g_qh : g_kh;
            __nv_bfloat16* dl = (t == 0) ? g_ql : g_kl;
            const float sc = (t == 0) ? 0.125f : 1.0f;
#pragma unroll
            for (int mt = 0; mt < 4; mt++)
#pragma unroll
                for (int nt = 0; nt < 4; nt++) {
                    const int colw = nn + wc * 32 + nt * 8 + cb;
                    float2 bv = *(const float2*)&bias[n0 + wc * 32 + nt * 8 + cb];
                    const size_t r0 = m0 + wr * 64 + mt * 16 + g;
                    uint32_t h0, l0, h1, l1;
                    split2((acc[mt][nt][0] + bv.x) * sc, (acc[mt][nt][1] + bv.y) * sc, h0, l0);
                    split2((acc[mt][nt][2] + bv.x) * sc, (acc[mt][nt][3] + bv.y) * sc, h1, l1);
                    *(uint32_t*)&dh[r0 * D_ + colw]       = h0;
                    *(uint32_t*)&dl[r0 * D_ + colw]       = l0;
                    *(uint32_t*)&dh[(r0 + 8) * D_ + colw] = h1;
                    *(uint32_t*)&dl[(r0 + 8) * D_ + colw] = l1;
                }
        } else {
            // V: stage split values TRANSPOSED in smem, then coalesced stores.
            // sm_h/sm_l: [col 0..127][row 0..127], stride 136 elements.
            __nv_bfloat16* sm_h = (__nv_bfloat16*)gsm;
            __nv_bfloat16* sm_l = sm_h + 128 * 136;   // 69632 B total <= 81920
#pragma unroll
            for (int mt = 0; mt < 4; mt++)
#pragma unroll
                for (int nt = 0; nt < 4; nt++) {
                    const int colw = wc * 32 + nt * 8 + cb;     // 0..126 (pair)
                    float2 bv = *(const float2*)&bias[n0 + colw];
                    const int rl = wr * 64 + mt * 16 + g;
                    __nv_bfloat16 hh, ll;
                    split1(acc[mt][nt][0] + bv.x, hh, ll);
                    sm_h[colw * 136 + rl] = hh;       sm_l[colw * 136 + rl] = ll;
                    split1(acc[mt][nt][1] + bv.y, hh, ll);
                    sm_h[(colw + 1) * 136 + rl] = hh; sm_l[(colw + 1) * 136 + rl] = ll;
                    split1(acc[mt][nt][2] + bv.x, hh, ll);
                    sm_h[colw * 136 + rl + 8] = hh;       sm_l[colw * 136 + rl + 8] = ll;
                    split1(acc[mt][nt][3] + bv.y, hh, ll);
                    sm_h[(colw + 1) * 136 + rl + 8] = hh; sm_l[(colw + 1) * 136 + rl + 8] = ll;
                }
            __syncthreads();
            const int bidx  = (int)(m0 / S_);
            const int m0loc = (int)(m0 % S_);
#pragma unroll
            for (int it = 0; it < 8; it++) {
                int idx = tid + it * 256;          // 0..2047
                int c = idx >> 4, sg = (idx & 15) * 8;
                int he = nn + c;
                int hh2 = he >> 6, e = he & 63;
                size_t ob = ((size_t)(bidx * H_ + hh2) * 64 + e) * S_ + m0loc + sg;
                *(uint4*)&g_vth[ob] = *(uint4*)&sm_h[c * 136 + sg];
                *(uint4*)&g_vtl[ob] = *(uint4*)&sm_l[c * 136 + sg];
            }
        }
    }
}

// ------------------- mma.sync bf16x3 causal flash attention -----------------
// Occ 1, Q frags in registers (proven best). Diagonal block-skipping: warps
// skip 16-wide k-blocks entirely above their rows on the two diagonal tiles.
#define PART_ 4608                 // elements per part (64*72)
#define BUF_  (4 * PART_)          // elements per KV buffer
__global__ __launch_bounds__(256, 1) void attn_mma_kernel() {
    extern __shared__ __align__(16) char dsm[];
    __nv_bfloat16* sm = (__nv_bfloat16*)dsm;
    const uint32_t sb = smem_u32(sm);

    const int tid = threadIdx.x, wid = tid >> 5, lane = tid & 31;
    const int qt = gridDim.x - 1 - blockIdx.x;
    const int bh = blockIdx.y;
    const int b = bh / H_, h = bh % H_;
    const int q0 = qt * 128;
    const int kmax = q0 + wid * 16 + 15;   // highest row this warp owns

#pragma unroll
    for (int it = 0; it < 8; it++) {
        int idx = tid + it * 256;
        int part = idx >> 10;
        int w = idx & 1023;
        int r = w >> 3, c8 = w & 7;
        const __nv_bfloat16* src = part ? g_ql : g_qh;
        *(uint4*)&sm[part * 9216 + r * 72 + c8 * 8] =
            *(const uint4*)&src[(size_t)(b * S_ + q0 + r) * D_ + h * 64 + c8 * 8];
    }
    __syncthreads();

    uint32_t aQh[4][4], aQl[4][4];
    {
        const int row = wid * 16 + (lane & 15);
        const int c8 = (lane >> 4) * 8;
#pragma unroll
        for (int kk = 0; kk < 4; kk++) {
            ldsm_x4(aQh[kk], sb + (row * 72 + kk * 16 + c8) * 2);
            ldsm_x4(aQl[kk], sb + (9216 + row * 72 + kk * 16 + c8) * 2);
        }
    }
    __syncthreads();

    float oacc[8][4] = {};
    float mrun[2] = {-1e30f, -1e30f}, lrun[2] = {0.0f, 0.0f};

    const int lrw = lane & 15;
    const int cb8 = (lane >> 4) * 8;
    const int ntiles = 2 * qt + 2;

    auto load_tile = [&](int kt, int bs) {
        const int k0 = kt * 64;
#pragma unroll
        for (int it = 0; it < 8; it++) {
            int idx = tid + it * 256;
            int part = idx >> 9;
            int w = idx & 511;
            int row = w >> 3, c8 = w & 7;
            uint32_t dst = sb + (bs * BUF_ + part * PART_ + row * 72 + c8 * 8) * 2;
            const __nv_bfloat16* src;
            if (part < 2) {
                const __nv_bfloat16* base = part ? g_kl : g_kh;
                src = &base[(size_t)(b * S_ + k0 + row) * D_ + h * 64 + c8 * 8];
            } else {
                const __nv_bfloat16* base = (part == 2) ? g_vth : g_vtl;
                src = &base[((size_t)bh * 64 + row) * S_ + k0 + c8 * 8];
            }
            CP_ASYNC16(dst, src);
        }
        CP_COMMIT();
    };

    load_tile(0, 0);

    for (int kt = 0; kt < ntiles; kt++) {
        const int bs = kt & 1;
        const int k0 = kt * 64;
        if (kt + 1 < ntiles) { load_tile(kt + 1, 1 - bs); CP_WAIT(1); }
        else                 { CP_WAIT(0); }
        __syncthreads();

        const uint32_t kbase = sb + (bs * BUF_) * 2;
        const uint32_t vbase = sb + (bs * BUF_ + 2 * PART_) * 2;

        // ---- S = Q K^T (bf16x3); skip k-blocks fully above this warp ----
        float sacc[8][4] = {};
#pragma unroll
        for (int kk = 0; kk < 4; kk++) {
#pragma unroll
            for (int np = 0; np < 4; np++) {
                if (k0 + np * 16 > kmax) continue;
                uint32_t kbh[4], kbl[4];
                ldsm_x4(kbh, kbase + ((np * 16 + lrw) * 72 + kk * 16 + cb8) * 2);
                ldsm_x4(kbl, kbase + (PART_ + (np * 16 + lrw) * 72 + kk * 16 + cb8) * 2);
#pragma unroll
                for (int ni = 0; ni < 2; ni++) {
                    const int nt = np * 2 + ni;
                    mma16816(sacc[nt], aQh[kk], kbh[ni], kbh[ni + 2]);
                    mma16816(sacc[nt], aQh[kk], kbl[ni], kbl[ni + 2]);
                    mma16816(sacc[nt], aQl[kk], kbh[ni], kbh[ni + 2]);
                }
            }
        }

        if (kt >= 2 * qt) {
#pragma unroll
            for (int nt = 0; nt < 8; nt++)
#pragma unroll
                for (int e = 0; e < 4; e++) {
                    const int row = q0 + wid * 16 + (lane >> 2) + (e >> 1) * 8;
                    const int col = k0 + nt * 8 + (lane & 3) * 2 + (e & 1);
                    if (col > row) sacc[nt][e] = -1e30f;
                }
        }

#pragma unroll
        for (int rg = 0; rg < 2; rg++) {
            float mloc = -1e30f;
#pragma unroll
            for (int nt = 0; nt < 8; nt++)
                mloc = fmaxf(mloc, fmaxf(sacc[nt][rg * 2], sacc[nt][rg * 2 + 1]));
            mloc = fmaxf(mloc, __shfl_xor_sync(0xffffffffu, mloc, 1));
            mloc = fmaxf(mloc, __shfl_xor_sync(0xffffffffu, mloc, 2));
            const float mnew = fmaxf(mrun[rg], mloc);
            const float alpha = __expf(mrun[rg] - mnew);
            float lloc = 0.0f;
#pragma unroll
            for (int nt = 0; nt < 8; nt++) {
                sacc[nt][rg * 2]     = __expf(sacc[nt][rg * 2] - mnew);
                sacc[nt][rg * 2 + 1] = __expf(sacc[nt][rg * 2 + 1] - mnew);
                lloc += sacc[nt][rg * 2] + sacc[nt][rg * 2 + 1];
            }
            lloc += __shfl_xor_sync(0xffffffffu, lloc, 1);
            lloc += __shfl_xor_sync(0xffffffffu, lloc, 2);
            lrun[rg] = lrun[rg] * alpha + lloc;
            mrun[rg] = mnew;
#pragma unroll
            for (int dt = 0; dt < 8; dt++) {
                oacc[dt][rg * 2]     *= alpha;
                oacc[dt][rg * 2 + 1] *= alpha;
            }
        }

        // ---- repack P -> A frags (hi/lo); skipped k-chunks stay unused ----
        uint32_t aPh[4][4], aPl[4][4];
#pragma unroll
        for (int k2 = 0; k2 < 4; k2++) {
            if (k0 + k2 * 16 > kmax) continue;
            split2(sacc[k2 * 2][0],     sacc[k2 * 2][1],     aPh[k2][0], aPl[k2][0]);
            split2(sacc[k2 * 2][2],     sacc[k2 * 2][3],     aPh[k2][1], aPl[k2][1]);
            split2(sacc[k2 * 2 + 1][0], sacc[k2 * 2 + 1][1], aPh[k2][2], aPl[k2][2]);
            split2(sacc[k2 * 2 + 1][2], sacc[k2 * 2 + 1][3], aPh[k2][3], aPl[k2][3]);
        }

        // ---- O += P V (bf16x3); skip fully-masked k-chunks (P == 0) ----
#pragma unroll
        for (int k2 = 0; k2 < 4; k2++) {
            if (k0 + k2 * 16 > kmax) continue;
#pragma unroll
            for (int dp = 0; dp < 4; dp++) {
                uint32_t vbh[4], vbl[4];
                ldsm_x4(vbh, vbase + ((dp * 16 + lrw) * 72 + k2 * 16 + cb8) * 2);
                ldsm_x4(vbl, vbase + (PART_ + (dp * 16 + lrw) * 72 + k2 * 16 + cb8) * 2);
#pragma unroll
                for (int ni = 0; ni < 2; ni++) {
                    const int dt = dp * 2 + ni;
                    mma16816(oacc[dt], aPh[k2], vbh[ni], vbh[ni + 2]);
                    mma16816(oacc[dt], aPh[k2], vbl[ni], vbl[ni + 2]);
                    mma16816(oacc[dt], aPl[k2], vbh[ni], vbh[ni + 2]);
                }
            }
        }
        __syncthreads();
    }

#pragma unroll
    for (int rg = 0; rg < 2; rg++) {
        const float inv = 1.0f / lrun[rg];
        const int row = q0 + wid * 16 + (lane >> 2) + rg * 8;
#pragma unroll
        for (int dt = 0; dt < 8; dt++) {
            const size_t o = (size_t)(b * S_ + row) * D_ + h * 64 + dt * 8 + (lane & 3) * 2;
            uint32_t hp, lp;
            split2(oacc[dt][rg * 2] * inv, oacc[dt][rg * 2 + 1] * inv, hp, lp);
            *(uint32_t*)&g_zh[o] = hp;
            *(uint32_t*)&g_zl[o] = lp;
        }
    }
}

// --------------------------------- launch ----------------------------------
extern "C" void kernel_launch(void* const* d_in, const int* in_sizes, int n_in,
                              void* d_out, int out_size) {
    const float* X  = (const float*)d_in[0];
    const float* Wq = (const float*)d_in[1];
    const float* Wk = (const float*)d_in[2];
    const float* Wv = (const float*)d_in[3];
    const float* Wo = (const float*)d_in[4];
    const float* bq = (const float*)d_in[5];
    const float* bk = (const float*)d_in[6];
    const float* bv = (const float*)d_in[7];
    const float* bo = (const float*)d_in[8];
    float* out = (float*)d_out;

    const int attn_smem = 2 * BUF_ * 2;     // 73728 B
    const int gemm_smem = 2 * GSTG_ * 2;    // 81920 B
    static bool attr_set = false;
    if (!attr_set) {
        cudaFuncSetAttribute(attn_mma_kernel,
                             cudaFuncAttributeMaxDynamicSharedMemorySize, attn_smem);
        cudaFuncSetAttribute(gemm_mma_kernel<0>,
                             cudaFuncAttributeMaxDynamicSharedMemorySize, gemm_smem);
        cudaFuncSetAttribute(gemm_mma_kernel<1>,
                             cudaFuncAttributeMaxDynamicSharedMemorySize, gemm_smem);
        attr_set = true;
    }

    static __nv_bfloat16 *xh = nullptr, *xl, *zh, *zl, *wth, *wtl, *woh, *wol;
    static float *fb;
    if (!xh) {
        cudaGetSymbolAddress((void**)&xh,  g_xh);
        cudaGetSymbolAddress((void**)&xl,  g_xl);
        cudaGetSymbolAddress((void**)&zh,  g_zh);
        cudaGetSymbolAddress((void**)&zl,  g_zl);
        cudaGetSymbolAddress((void**)&wth, g_wth);
        cudaGetSymbolAddress((void**)&wtl, g_wtl);
        cudaGetSymbolAddress((void**)&woh, g_woh);
        cudaGetSymbolAddress((void**)&wol, g_wol);
        cudaGetSymbolAddress((void**)&fb,  g_fb);
    }

    // 1) conversions
    split_kernel<<<(M_ * D_) / (256 * 8), 256>>>(X, xh, xl, M_ * D_);
    trans_qkv_kernel<<<dim3(D_ / 64, 3 * H_), 256>>>(Wq, Wk, Wv, bq, bk, bv);
    trans_wo_kernel<<<dim3(D_ / 64, D_ / 64), 256>>>(Wo);

    // 2) fused QKV projection -> q/k split bf16 + V transposed split bf16
    gemm_mma_kernel<1><<<dim3(NF_ / 128, M_ / 128), 256, gemm_smem>>>(
        xh, xl, wth, wtl, nullptr, 0, fb);

    // 3) causal attention (tensor cores, diagonal block-skipping)
    attn_mma_kernel<<<dim3(S_ / 128, B_ * H_), 256, attn_smem>>>();

    // 4) output projection
    gemm_mma_kernel<0><<<dim3(D_ / 128, M_ / 128), 256, gemm_smem>>>(
        zh, zl, woh, wol, out, D_, bo);
}

// round 12
// speedup vs baseline: 1.0812x; 1.0736x over previous
#include <cuda_runtime.h>
#include <cuda_bf16.h>
#include <cstdint>

#define B_  4
#define S_  2048
#define D_  768
#define H_  12
#define M_  (B_ * S_)     // 8192
#define NF_ (3 * D_)      // 2304 fused qkv cols

// ------------------------- device scratch (no allocs) -----------------------
__device__ __nv_bfloat16  g_xh [(size_t)M_ * D_];    // residual hi/lo
__device__ __nv_bfloat16  g_xl [(size_t)M_ * D_];
__device__ __nv_bfloat16  g_qh [(size_t)M_ * D_];    // q (pre-scaled) hi/lo
__device__ __nv_bfloat16  g_ql [(size_t)M_ * D_];
__device__ __nv_bfloat16  g_kh [(size_t)M_ * D_];    // k hi/lo
__device__ __nv_bfloat16  g_kl [(size_t)M_ * D_];
__device__ __nv_bfloat16  g_vth[(size_t)B_ * H_ * 64 * S_];  // v^T [bh][dh][s]
__device__ __nv_bfloat16  g_vtl[(size_t)B_ * H_ * 64 * S_];
__device__ __nv_bfloat16  g_zh [(size_t)M_ * D_];    // attention out hi/lo
__device__ __nv_bfloat16  g_zl [(size_t)M_ * D_];
__device__ __nv_bfloat16  g_wth[(size_t)NF_ * D_];   // W_{q,k,v}^T  [n][d]
__device__ __nv_bfloat16  g_wtl[(size_t)NF_ * D_];
__device__ __nv_bfloat16  g_woh[(size_t)D_ * D_];    // W_O^T [d_out][he]
__device__ __nv_bfloat16  g_wol[(size_t)D_ * D_];
__device__ float          g_fb [NF_];                // fused qkv bias

// ------------------------------ PTX helpers --------------------------------
__device__ __forceinline__ uint32_t smem_u32(const void* p) {
    uint32_t a;
    asm("{ .reg .u64 t; cvta.to.shared.u64 t, %1; cvt.u32.u64 %0, t; }"
        : "=r"(a) : "l"(p));
    return a;
}
__device__ __forceinline__ void ldsm_x4(uint32_t* r, uint32_t addr) {
    asm volatile("ldmatrix.sync.aligned.m8n8.x4.shared.b16 {%0,%1,%2,%3}, [%4];"
                 : "=r"(r[0]), "=r"(r[1]), "=r"(r[2]), "=r"(r[3]) : "r"(addr));
}
__device__ __forceinline__ void mma16816(float* c, const uint32_t* a,
                                         uint32_t b0, uint32_t b1) {
    asm volatile(
        "mma.sync.aligned.m16n8k16.row.col.f32.bf16.bf16.f32 "
        "{%0,%1,%2,%3}, {%4,%5,%6,%7}, {%8,%9}, {%0,%1,%2,%3};"
        : "+f"(c[0]), "+f"(c[1]), "+f"(c[2]), "+f"(c[3])
        : "r"(a[0]), "r"(a[1]), "r"(a[2]), "r"(a[3]), "r"(b0), "r"(b1));
}
__device__ __forceinline__ void split2(float a, float b, uint32_t& hi, uint32_t& lo) {
    __nv_bfloat16 ha = __float2bfloat16(a), hb = __float2bfloat16(b);
    __nv_bfloat16 la = __float2bfloat16(a - __bfloat162float(ha));
    __nv_bfloat16 lb = __float2bfloat16(b - __bfloat162float(hb));
    __nv_bfloat162 hp = {ha, hb}, lp = {la, lb};
    hi = *(uint32_t*)&hp; lo = *(uint32_t*)&lp;
}
__device__ __forceinline__ void split1(float v, __nv_bfloat16& h, __nv_bfloat16& l) {
    h = __float2bfloat16(v);
    l = __float2bfloat16(v - __bfloat162float(h));
}
#define CP_ASYNC16(dst, src) \
    asm volatile("cp.async.cg.shared.global [%0], [%1], 16;" :: "r"(dst), "l"(src))
#define CP_COMMIT() asm volatile("cp.async.commit_group;" ::: "memory")
#define CP_WAIT(n)  asm volatile("cp.async.wait_group %0;" :: "n"(n) : "memory")

// --------------------------- conversion kernels ----------------------------
__global__ void split_kernel(const float* __restrict__ src,
                             __nv_bfloat16* __restrict__ dh,
                             __nv_bfloat16* __restrict__ dl, int n) {
    int i8 = (blockIdx.x * 256 + threadIdx.x) * 8;
    if (i8 >= n) return;
    float4 v0 = *(const float4*)&src[i8];
    float4 v1 = *(const float4*)&src[i8 + 4];
    float v[8] = {v0.x, v0.y, v0.z, v0.w, v1.x, v1.y, v1.z, v1.w};
    __align__(16) __nv_bfloat16 h[8], l[8];
#pragma unroll
    for (int j = 0; j < 8; j++) {
        h[j] = __float2bfloat16(v[j]);
        l[j] = __float2bfloat16(v[j] - __bfloat162float(h[j]));
    }
    *(uint4*)&dh[i8] = *(uint4*)h;
    *(uint4*)&dl[i8] = *(uint4*)l;
}

__device__ __forceinline__ void trans_tile(const float* src, int src_ld,
                                           __nv_bfloat16* dh, __nv_bfloat16* dl,
                                           int dst_ld, int r0, int c0, int base) {
    __shared__ float ts[64 * 65];
    const int tid = threadIdx.x;
#pragma unroll
    for (int it = 0; it < 16; it++) {
        int flat = tid + it * 256;
        int i = flat >> 6, c = flat & 63;
        ts[c * 65 + i] = src[(size_t)(r0 + i) * src_ld + c0 + c];
    }
    __syncthreads();
#pragma unroll
    for (int it = 0; it < 8; it++) {
        int flat = tid + it * 256;
        int c = flat >> 5, rj = flat & 31;
        uint32_t hp, lp;
        split2(ts[c * 65 + rj * 2], ts[c * 65 + rj * 2 + 1], hp, lp);
        size_t o = (size_t)(base + c0 + c) * dst_ld + r0 + rj * 2;
        *(uint32_t*)&dh[o] = hp;
        *(uint32_t*)&dl[o] = lp;
    }
}

__global__ void trans_qkv_kernel(const float* __restrict__ Wq,
                                 const float* __restrict__ Wk,
                                 const float* __restrict__ Wv,
                                 const float* __restrict__ bq,
                                 const float* __restrict__ bk,
                                 const float* __restrict__ bv) {
    const int by = blockIdx.y;
    const int t = by / H_, h = by % H_;
    if (blockIdx.x == 0 && threadIdx.x < 64) {
        const float* bp = (t == 0) ? bq : (t == 1) ? bk : bv;
        g_fb[t * D_ + h * 64 + threadIdx.x] = bp[h * 64 + threadIdx.x];
    }
    const float* src = ((t == 0) ? Wq : (t == 1) ? Wk : Wv) + (size_t)h * D_ * 64;
    trans_tile(src, 64, g_wth, g_wtl, D_, blockIdx.x * 64, 0, t * D_ + h * 64);
}
__global__ void trans_wo_kernel(const float* __restrict__ Wo) {
    trans_tile(Wo, D_, g_woh, g_wol, D_, blockIdx.x * 64, blockIdx.y * 64, 0);
}

// ------------------------ mma.sync bf16x3 GEMM ------------------------------
// cp.async double-buffered, occ 2 (proven best). BK=32, CTA 128x128, 8 warps.
// MODE 0: fp32 out + bias. MODE 1: split bf16 q/k natural; V transposed via
// smem-staged coalesced epilogue (fused trans_v).
#define GP_   5120                 // elements per part (128*40)
#define GSTG_ (4 * GP_)            // elements per stage
template <int MODE>
__global__ __launch_bounds__(256, 2)
void gemm_mma_kernel(const __nv_bfloat16* __restrict__ Ah,
                     const __nv_bfloat16* __restrict__ Al,
                     const __nv_bfloat16* __restrict__ Bh,
                     const __nv_bfloat16* __restrict__ Bl,
                     float* __restrict__ out, int ld_out,
                     const float* __restrict__ bias) {
    extern __shared__ __align__(16) char gsm[];
    const uint32_t sb = smem_u32(gsm);

    const int tid  = threadIdx.x;
    const int wid  = tid >> 5;
    const int lane = tid & 31;
    const int wr   = wid >> 2;
    const int wc   = wid & 3;
    const size_t m0 = blockIdx.y * 128;
    const size_t n0 = blockIdx.x * 128;

    const __nv_bfloat16* srcs[4] = {Ah, Al, Bh, Bl};
    const size_t rbase[4] = {m0, m0, n0, n0};

    auto load_st = [&](int kt, int st) {
        const int k0 = kt * 32;
#pragma unroll
        for (int it = 0; it < 8; it++) {
            int idx = tid + it * 256;
            int part = idx >> 9;
            int w = idx & 511;
            int row = w >> 2, c8 = w & 3;
            uint32_t dst = sb + (st * GSTG_ + part * GP_ + row * 40 + c8 * 8) * 2;
            const __nv_bfloat16* src =
                &srcs[part][(rbase[part] + row) * D_ + k0 + c8 * 8];
            CP_ASYNC16(dst, src);
        }
        CP_COMMIT();
    };

    float acc[4][4][4] = {};

    const int lrow = lane & 15;
    const int lcol = (lane >> 4) * 8;

    load_st(0, 0);

    for (int kt = 0; kt < 24; kt++) {
        const int st = kt & 1;
        if (kt < 23) { load_st(kt + 1, 1 - st); CP_WAIT(1); }
        else         { CP_WAIT(0); }
        __syncthreads();

        const uint32_t s0 = sb + (st * GSTG_) * 2;
#pragma unroll
        for (int ks = 0; ks < 2; ks++) {
            const int kb = ks * 16;
            const uint32_t arow = s0 + ((wr * 64 + lrow) * 40 + kb + lcol) * 2;
            const uint32_t brow = s0 + ((wc * 32 + lrow) * 40 + kb + lcol) * 2;

            uint32_t aF[4][4], bFh[2][4], bF2[2][4];
#pragma unroll
            for (int mt = 0; mt < 4; mt++)
                ldsm_x4(aF[mt], arow + (0 * GP_ + mt * 16 * 40) * 2);
#pragma unroll
            for (int np = 0; np < 2; np++)
                ldsm_x4(bFh[np], brow + (2 * GP_ + np * 16 * 40) * 2);
#pragma unroll
            for (int mt = 0; mt < 4; mt++)
#pragma unroll
                for (int nt = 0; nt < 4; nt++)
                    mma16816(acc[mt][nt], aF[mt], bFh[nt >> 1][nt & 1],
                             bFh[nt >> 1][(nt & 1) + 2]);
#pragma unroll
            for (int np = 0; np < 2; np++)
                ldsm_x4(bF2[np], brow + (3 * GP_ + np * 16 * 40) * 2);
#pragma unroll
            for (int mt = 0; mt < 4; mt++)
#pragma unroll
                for (int nt = 0; nt < 4; nt++)
                    mma16816(acc[mt][nt], aF[mt], bF2[nt >> 1][nt & 1],
                             bF2[nt >> 1][(nt & 1) + 2]);
#pragma unroll
            for (int mt = 0; mt < 4; mt++)
                ldsm_x4(aF[mt], arow + (1 * GP_ + mt * 16 * 40) * 2);
#pragma unroll
            for (int mt = 0; mt < 4; mt++)
#pragma unroll
                for (int nt = 0; nt < 4; nt++)
                    mma16816(acc[mt][nt], aF[mt], bFh[nt >> 1][nt & 1],
                             bFh[nt >> 1][(nt & 1) + 2]);
        }
        __syncthreads();
    }

    const int g = lane >> 2;
    const int cb = (lane & 3) * 2;

    if (MODE == 0) {
#pragma unroll
        for (int mt = 0; mt < 4; mt++)
#pragma unroll
            for (int nt = 0; nt < 4; nt++) {
                const size_t col = n0 + wc * 32 + nt * 8 + cb;
                float2 bv = *(const float2*)&bias[col];
                const size_t r0 = m0 + wr * 64 + mt * 16 + g;
                float2 v0 = {acc[mt][nt][0] + bv.x, acc[mt][nt][1] + bv.y};
                float2 v1 = {acc[mt][nt][2] + bv.x, acc[mt][nt][3] + bv.y};
                *(float2*)&out[r0 * ld_out + col]       = v0;
                *(float2*)&out[(r0 + 8) * ld_out + col] = v1;
            }
    } else {
        const int t  = (int)(n0 / D_);
        const int nn = (int)(n0 - t * D_);
        if (t < 2) {
            __nv_bfloat16* dh = (t == 0) ? g_qh : g_kh;
            __nv_bfloat16* dl = (t == 0) ? g_ql : g_kl;
            const float sc = (t == 0) ? 0.125f : 1.0f;
#pragma unroll
            for (int mt = 0; mt < 4; mt++)
#pragma unroll
                for (int nt = 0; nt < 4; nt++) {
                    const int colw = nn + wc * 32 + nt * 8 + cb;
                    float2 bv = *(const float2*)&bias[n0 + wc * 32 + nt * 8 + cb];
                    const size_t r0 = m0 + wr * 64 + mt * 16 + g;
                    uint32_t h0, l0, h1, l1;
                    split2((acc[mt][nt][0] + bv.x) * sc, (acc[mt][nt][1] + bv.y) * sc, h0, l0);
                    split2((acc[mt][nt][2] + bv.x) * sc, (acc[mt][nt][3] + bv.y) * sc, h1, l1);
                    *(uint32_t*)&dh[r0 * D_ + colw]       = h0;
                    *(uint32_t*)&dl[r0 * D_ + colw]       = l0;
                    *(uint32_t*)&dh[(r0 + 8) * D_ + colw] = h1;
                    *(uint32_t*)&dl[(r0 + 8) * D_ + colw] = l1;
                }
        } else {
            // V: stage split values TRANSPOSED in smem, then coalesced stores.
            __nv_bfloat16* sm_h = (__nv_bfloat16*)gsm;
            __nv_bfloat16* sm_l = sm_h + 128 * 136;   // 69632 B total <= 81920
#pragma unroll
            for (int mt = 0; mt < 4; mt++)
#pragma unroll
                for (int nt = 0; nt < 4; nt++) {
                    const int colw = wc * 32 + nt * 8 + cb;     // 0..126 (pair)
                    float2 bv = *(const float2*)&bias[n0 + colw];
                    const int rl = wr * 64 + mt * 16 + g;
                    __nv_bfloat16 hh, ll;
                    split1(acc[mt][nt][0] + bv.x, hh, ll);
                    sm_h[colw * 136 + rl] = hh;       sm_l[colw * 136 + rl] = ll;
                    split1(acc[mt][nt][1] + bv.y, hh, ll);
                    sm_h[(colw + 1) * 136 + rl] = hh; sm_l[(colw + 1) * 136 + rl] = ll;
                    split1(acc[mt][nt][2] + bv.x, hh, ll);
                    sm_h[colw * 136 + rl + 8] = hh;       sm_l[colw * 136 + rl + 8] = ll;
                    split1(acc[mt][nt][3] + bv.y, hh, ll);
                    sm_h[(colw + 1) * 136 + rl + 8] = hh; sm_l[(colw + 1) * 136 + rl + 8] = ll;
                }
            __syncthreads();
            const int bidx  = (int)(m0 / S_);
            const int m0loc = (int)(m0 % S_);
#pragma unroll
            for (int it = 0; it < 8; it++) {
                int idx = tid + it * 256;          // 0..2047
                int c = idx >> 4, sg = (idx & 15) * 8;
                int he = nn + c;
                int hh2 = he >> 6, e = he & 63;
                size_t ob = ((size_t)(bidx * H_ + hh2) * 64 + e) * S_ + m0loc + sg;
                *(uint4*)&g_vth[ob] = *(uint4*)&sm_h[c * 136 + sg];
                *(uint4*)&g_vtl[ob] = *(uint4*)&sm_l[c * 136 + sg];
            }
        }
    }
}

// ------------------- mma.sync bf16x3 causal flash attention (R8 exact) ------
#define PART_ 4608                 // elements per part (64*72)
#define BUF_  (4 * PART_)          // elements per KV buffer
__global__ __launch_bounds__(256, 1) void attn_mma_kernel() {
    extern __shared__ __align__(16) char dsm[];
    __nv_bfloat16* sm = (__nv_bfloat16*)dsm;
    const uint32_t sb = smem_u32(sm);

    const int tid = threadIdx.x, wid = tid >> 5, lane = tid & 31;
    const int qt = gridDim.x - 1 - blockIdx.x;
    const int bh = blockIdx.y;
    const int b = bh / H_, h = bh % H_;
    const int q0 = qt * 128;

#pragma unroll
    for (int it = 0; it < 8; it++) {
        int idx = tid + it * 256;
        int part = idx >> 10;
        int w = idx & 1023;
        int r = w >> 3, c8 = w & 7;
        const __nv_bfloat16* src = part ? g_ql : g_qh;
        *(uint4*)&sm[part * 9216 + r * 72 + c8 * 8] =
            *(const uint4*)&src[(size_t)(b * S_ + q0 + r) * D_ + h * 64 + c8 * 8];
    }
    __syncthreads();

    uint32_t aQh[4][4], aQl[4][4];
    {
        const int row = wid * 16 + (lane & 15);
        const int c8 = (lane >> 4) * 8;
#pragma unroll
        for (int kk = 0; kk < 4; kk++) {
            ldsm_x4(aQh[kk], sb + (row * 72 + kk * 16 + c8) * 2);
            ldsm_x4(aQl[kk], sb + (9216 + row * 72 + kk * 16 + c8) * 2);
        }
    }
    __syncthreads();

    float oacc[8][4] = {};
    float mrun[2] = {-1e30f, -1e30f}, lrun[2] = {0.0f, 0.0f};

    const int lrw = lane & 15;
    const int cb8 = (lane >> 4) * 8;
    const int ntiles = 2 * qt + 2;

    auto load_tile = [&](int kt, int bs) {
        const int k0 = kt * 64;
#pragma unroll
        for (int it = 0; it < 8; it++) {
            int idx = tid + it * 256;
            int part = idx >> 9;
            int w = idx & 511;
            int row = w >> 3, c8 = w & 7;
            uint32_t dst = sb + (bs * BUF_ + part * PART_ + row * 72 + c8 * 8) * 2;
            const __nv_bfloat16* src;
            if (part < 2) {
                const __nv_bfloat16* base = part ? g_kl : g_kh;
                src = &base[(size_t)(b * S_ + k0 + row) * D_ + h * 64 + c8 * 8];
            } else {
                const __nv_bfloat16* base = (part == 2) ? g_vth : g_vtl;
                src = &base[((size_t)bh * 64 + row) * S_ + k0 + c8 * 8];
            }
            CP_ASYNC16(dst, src);
        }
        CP_COMMIT();
    };

    load_tile(0, 0);

    for (int kt = 0; kt < ntiles; kt++) {
        const int bs = kt & 1;
        if (kt + 1 < ntiles) { load_tile(kt + 1, 1 - bs); CP_WAIT(1); }
        else                 { CP_WAIT(0); }
        __syncthreads();

        const uint32_t kbase = sb + (bs * BUF_) * 2;
        const uint32_t vbase = sb + (bs * BUF_ + 2 * PART_) * 2;

        float sacc[8][4] = {};
#pragma unroll
        for (int kk = 0; kk < 4; kk++) {
#pragma unroll
            for (int np = 0; np < 4; np++) {
                uint32_t kbh[4], kbl[4];
                ldsm_x4(kbh, kbase + ((np * 16 + lrw) * 72 + kk * 16 + cb8) * 2);
                ldsm_x4(kbl, kbase + (PART_ + (np * 16 + lrw) * 72 + kk * 16 + cb8) * 2);
#pragma unroll
                for (int ni = 0; ni < 2; ni++) {
                    const int nt = np * 2 + ni;
                    mma16816(sacc[nt], aQh[kk], kbh[ni], kbh[ni + 2]);
                    mma16816(sacc[nt], aQh[kk], kbl[ni], kbl[ni + 2]);
                    mma16816(sacc[nt], aQl[kk], kbh[ni], kbh[ni + 2]);
                }
            }
        }

        const int k0 = kt * 64;
        if (kt >= 2 * qt) {
#pragma unroll
            for (int nt = 0; nt < 8; nt++)
#pragma unroll
                for (int e = 0; e < 4; e++) {
                    const int row = q0 + wid * 16 + (lane >> 2) + (e >> 1) * 8;
                    const int col = k0 + nt * 8 + (lane & 3) * 2 + (e & 1);
                    if (col > row) sacc[nt][e] = -1e30f;
                }
        }

#pragma unroll
        for (int rg = 0; rg < 2; rg++) {
            float mloc = -1e30f;
#pragma unroll
            for (int nt = 0; nt < 8; nt++)
                mloc = fmaxf(mloc, fmaxf(sacc[nt][rg * 2], sacc[nt][rg * 2 + 1]));
            mloc = fmaxf(mloc, __shfl_xor_sync(0xffffffffu, mloc, 1));
            mloc = fmaxf(mloc, __shfl_xor_sync(0xffffffffu, mloc, 2));
            const float mnew = fmaxf(mrun[rg], mloc);
            const float alpha = __expf(mrun[rg] - mnew);
            float lloc = 0.0f;
#pragma unroll
            for (int nt = 0; nt < 8; nt++) {
                sacc[nt][rg * 2]     = __expf(sacc[nt][rg * 2] - mnew);
                sacc[nt][rg * 2 + 1] = __expf(sacc[nt][rg * 2 + 1] - mnew);
                lloc += sacc[nt][rg * 2] + sacc[nt][rg * 2 + 1];
            }
            lloc += __shfl_xor_sync(0xffffffffu, lloc, 1);
            lloc += __shfl_xor_sync(0xffffffffu, lloc, 2);
            lrun[rg] = lrun[rg] * alpha + lloc;
            mrun[rg] = mnew;
#pragma unroll
            for (int dt = 0; dt < 8; dt++) {
                oacc[dt][rg * 2]     *= alpha;
                oacc[dt][rg * 2 + 1] *= alpha;
            }
        }

        uint32_t aPh[4][4], aPl[4][4];
#pragma unroll
        for (int k2 = 0; k2 < 4; k2++) {
            split2(sacc[k2 * 2][0],     sacc[k2 * 2][1],     aPh[k2][0], aPl[k2][0]);
            split2(sacc[k2 * 2][2],     sacc[k2 * 2][3],     aPh[k2][1], aPl[k2][1]);
            split2(sacc[k2 * 2 + 1][0], sacc[k2 * 2 + 1][1], aPh[k2][2], aPl[k2][2]);
            split2(sacc[k2 * 2 + 1][2], sacc[k2 * 2 + 1][3], aPh[k2][3], aPl[k2][3]);
        }

#pragma unroll
        for (int k2 = 0; k2 < 4; k2++) {
#pragma unroll
            for (int dp = 0; dp < 4; dp++) {
                uint32_t vbh[4], vbl[4];
                ldsm_x4(vbh, vbase + ((dp * 16 + lrw) * 72 + k2 * 16 + cb8) * 2);
                ldsm_x4(vbl, vbase + (PART_ + (dp * 16 + lrw) * 72 + k2 * 16 + cb8) * 2);
#pragma unroll
                for (int ni = 0; ni < 2; ni++) {
                    const int dt = dp * 2 + ni;
                    mma16816(oacc[dt], aPh[k2], vbh[ni], vbh[ni + 2]);
                    mma16816(oacc[dt], aPh[k2], vbl[ni], vbl[ni + 2]);
                    mma16816(oacc[dt], aPl[k2], vbh[ni], vbh[ni + 2]);
                }
            }
        }
        __syncthreads();
    }

#pragma unroll
    for (int rg = 0; rg < 2; rg++) {
        const float inv = 1.0f / lrun[rg];
        const int row = q0 + wid * 16 + (lane >> 2) + rg * 8;
#pragma unroll
        for (int dt = 0; dt < 8; dt++) {
            const size_t o = (size_t)(b * S_ + row) * D_ + h * 64 + dt * 8 + (lane & 3) * 2;
            uint32_t hp, lp;
            split2(oacc[dt][rg * 2] * inv, oacc[dt][rg * 2 + 1] * inv, hp, lp);
            *(uint32_t*)&g_zh[o] = hp;
            *(uint32_t*)&g_zl[o] = lp;
        }
    }
}

// --------------------------------- launch ----------------------------------
extern "C" void kernel_launch(void* const* d_in, const int* in_sizes, int n_in,
                              void* d_out, int out_size) {
    const float* X  = (const float*)d_in[0];
    const float* Wq = (const float*)d_in[1];
    const float* Wk = (const float*)d_in[2];
    const float* Wv = (const float*)d_in[3];
    const float* Wo = (const float*)d_in[4];
    const float* bq = (const float*)d_in[5];
    const float* bk = (const float*)d_in[6];
    const float* bv = (const float*)d_in[7];
    const float* bo = (const float*)d_in[8];
    float* out = (float*)d_out;

    const int attn_smem = 2 * BUF_ * 2;     // 73728 B
    const int gemm_smem = 2 * GSTG_ * 2;    // 81920 B
    static bool attr_set = false;
    if (!attr_set) {
        cudaFuncSetAttribute(attn_mma_kernel,
                             cudaFuncAttributeMaxDynamicSharedMemorySize, attn_smem);
        cudaFuncSetAttribute(gemm_mma_kernel<0>,
                             cudaFuncAttributeMaxDynamicSharedMemorySize, gemm_smem);
        cudaFuncSetAttribute(gemm_mma_kernel<1>,
                             cudaFuncAttributeMaxDynamicSharedMemorySize, gemm_smem);
        attr_set = true;
    }

    static __nv_bfloat16 *xh = nullptr, *xl, *zh, *zl, *wth, *wtl, *woh, *wol;
    static float *fb;
    if (!xh) {
        cudaGetSymbolAddress((void**)&xh,  g_xh);
        cudaGetSymbolAddress((void**)&xl,  g_xl);
        cudaGetSymbolAddress((void**)&zh,  g_zh);
        cudaGetSymbolAddress((void**)&zl,  g_zl);
        cudaGetSymbolAddress((void**)&wth, g_wth);
        cudaGetSymbolAddress((void**)&wtl, g_wtl);
        cudaGetSymbolAddress((void**)&woh, g_woh);
        cudaGetSymbolAddress((void**)&wol, g_wol);
        cudaGetSymbolAddress((void**)&fb,  g_fb);
    }

    // 1) conversions
    split_kernel<<<(M_ * D_) / (256 * 8), 256>>>(X, xh, xl, M_ * D_);
    trans_qkv_kernel<<<dim3(D_ / 64, 3 * H_), 256>>>(Wq, Wk, Wv, bq, bk, bv);
    trans_wo_kernel<<<dim3(D_ / 64, D_ / 64), 256>>>(Wo);

    // 2) fused QKV projection -> q/k split bf16 + V transposed split bf16
    gemm_mma_kernel<1><<<dim3(NF_ / 128, M_ / 128), 256, gemm_smem>>>(
        xh, xl, wth, wtl, nullptr, 0, fb);

    // 3) causal attention (tensor cores, straight-line loops)
    attn_mma_kernel<<<dim3(S_ / 128, B_ * H_), 256, attn_smem>>>();

    // 4) output projection
    gemm_mma_kernel<0><<<dim3(D_ / 128, M_ / 128), 256, gemm_smem>>>(
        zh, zl, woh, wol, out, D_, bo);
}

// round 13
// speedup vs baseline: 1.0968x; 1.0144x over previous
#include <cuda_runtime.h>
#include <cuda_bf16.h>
#include <cstdint>

#define B_  4
#define S_  2048
#define D_  768
#define H_  12
#define M_  (B_ * S_)     // 8192
#define NF_ (3 * D_)      // 2304 fused qkv cols

// ------------------------- device scratch (no allocs) -----------------------
__device__ __nv_bfloat16  g_xh [(size_t)M_ * D_];    // residual hi/lo
__device__ __nv_bfloat16  g_xl [(size_t)M_ * D_];
__device__ __nv_bfloat16  g_qh [(size_t)M_ * D_];    // q (pre-scaled by 0.125*log2e) hi/lo
__device__ __nv_bfloat16  g_ql [(size_t)M_ * D_];
__device__ __nv_bfloat16  g_kh [(size_t)M_ * D_];    // k hi/lo
__device__ __nv_bfloat16  g_kl [(size_t)M_ * D_];
__device__ __nv_bfloat16  g_vth[(size_t)B_ * H_ * 64 * S_];  // v^T [bh][dh][s]
__device__ __nv_bfloat16  g_vtl[(size_t)B_ * H_ * 64 * S_];
__device__ __nv_bfloat16  g_zh [(size_t)M_ * D_];    // attention out hi/lo
__device__ __nv_bfloat16  g_zl [(size_t)M_ * D_];
__device__ __nv_bfloat16  g_wth[(size_t)NF_ * D_];   // W_{q,k,v}^T  [n][d]
__device__ __nv_bfloat16  g_wtl[(size_t)NF_ * D_];
__device__ __nv_bfloat16  g_woh[(size_t)D_ * D_];    // W_O^T [d_out][he]
__device__ __nv_bfloat16  g_wol[(size_t)D_ * D_];
__device__ float          g_fb [NF_];                // fused qkv bias

// ------------------------------ PTX helpers --------------------------------
__device__ __forceinline__ uint32_t smem_u32(const void* p) {
    uint32_t a;
    asm("{ .reg .u64 t; cvta.to.shared.u64 t, %1; cvt.u32.u64 %0, t; }"
        : "=r"(a) : "l"(p));
    return a;
}
__device__ __forceinline__ void ldsm_x4(uint32_t* r, uint32_t addr) {
    asm volatile("ldmatrix.sync.aligned.m8n8.x4.shared.b16 {%0,%1,%2,%3}, [%4];"
                 : "=r"(r[0]), "=r"(r[1]), "=r"(r[2]), "=r"(r[3]) : "r"(addr));
}
__device__ __forceinline__ void mma16816(float* c, const uint32_t* a,
                                         uint32_t b0, uint32_t b1) {
    asm volatile(
        "mma.sync.aligned.m16n8k16.row.col.f32.bf16.bf16.f32 "
        "{%0,%1,%2,%3}, {%4,%5,%6,%7}, {%8,%9}, {%0,%1,%2,%3};"
        : "+f"(c[0]), "+f"(c[1]), "+f"(c[2]), "+f"(c[3])
        : "r"(a[0]), "r"(a[1]), "r"(a[2]), "r"(a[3]), "r"(b0), "r"(b1));
}
__device__ __forceinline__ float ex2f(float x) {
    float y;
    asm("ex2.approx.f32 %0, %1;" : "=f"(y) : "f"(x));
    return y;
}
__device__ __forceinline__ void split2(float a, float b, uint32_t& hi, uint32_t& lo) {
    __nv_bfloat16 ha = __float2bfloat16(a), hb = __float2bfloat16(b);
    __nv_bfloat16 la = __float2bfloat16(a - __bfloat162float(ha));
    __nv_bfloat16 lb = __float2bfloat16(b - __bfloat162float(hb));
    __nv_bfloat162 hp = {ha, hb}, lp = {la, lb};
    hi = *(uint32_t*)&hp; lo = *(uint32_t*)&lp;
}
__device__ __forceinline__ void split1(float v, __nv_bfloat16& h, __nv_bfloat16& l) {
    h = __float2bfloat16(v);
    l = __float2bfloat16(v - __bfloat162float(h));
}
#define CP_ASYNC16(dst, src) \
    asm volatile("cp.async.cg.shared.global [%0], [%1], 16;" :: "r"(dst), "l"(src))
#define CP_COMMIT() asm volatile("cp.async.commit_group;" ::: "memory")
#define CP_WAIT(n)  asm volatile("cp.async.wait_group %0;" :: "n"(n) : "memory")

// --------------------------- conversion kernels ----------------------------
__global__ void split_kernel(const float* __restrict__ src,
                             __nv_bfloat16* __restrict__ dh,
                             __nv_bfloat16* __restrict__ dl, int n) {
    int i8 = (blockIdx.x * 256 + threadIdx.x) * 8;
    if (i8 >= n) return;
    float4 v0 = *(const float4*)&src[i8];
    float4 v1 = *(const float4*)&src[i8 + 4];
    float v[8] = {v0.x, v0.y, v0.z, v0.w, v1.x, v1.y, v1.z, v1.w};
    __align__(16) __nv_bfloat16 h[8], l[8];
#pragma unroll
    for (int j = 0; j < 8; j++) {
        h[j] = __float2bfloat16(v[j]);
        l[j] = __float2bfloat16(v[j] - __bfloat162float(h[j]));
    }
    *(uint4*)&dh[i8] = *(uint4*)h;
    *(uint4*)&dl[i8] = *(uint4*)l;
}

__device__ __forceinline__ void trans_tile(const float* src, int src_ld,
                                           __nv_bfloat16* dh, __nv_bfloat16* dl,
                                           int dst_ld, int r0, int c0, int base) {
    __shared__ float ts[64 * 65];
    const int tid = threadIdx.x;
#pragma unroll
    for (int it = 0; it < 16; it++) {
        int flat = tid + it * 256;
        int i = flat >> 6, c = flat & 63;
        ts[c * 65 + i] = src[(size_t)(r0 + i) * src_ld + c0 + c];
    }
    __syncthreads();
#pragma unroll
    for (int it = 0; it < 8; it++) {
        int flat = tid + it * 256;
        int c = flat >> 5, rj = flat & 31;
        uint32_t hp, lp;
        split2(ts[c * 65 + rj * 2], ts[c * 65 + rj * 2 + 1], hp, lp);
        size_t o = (size_t)(base + c0 + c) * dst_ld + r0 + rj * 2;
        *(uint32_t*)&dh[o] = hp;
        *(uint32_t*)&dl[o] = lp;
    }
}

__global__ void trans_qkv_kernel(const float* __restrict__ Wq,
                                 const float* __restrict__ Wk,
                                 const float* __restrict__ Wv,
                                 const float* __restrict__ bq,
                                 const float* __restrict__ bk,
                                 const float* __restrict__ bv) {
    const int by = blockIdx.y;
    const int t = by / H_, h = by % H_;
    if (blockIdx.x == 0 && threadIdx.x < 64) {
        const float* bp = (t == 0) ? bq : (t == 1) ? bk : bv;
        g_fb[t * D_ + h * 64 + threadIdx.x] = bp[h * 64 + threadIdx.x];
    }
    const float* src = ((t == 0) ? Wq : (t == 1) ? Wk : Wv) + (size_t)h * D_ * 64;
    trans_tile(src, 64, g_wth, g_wtl, D_, blockIdx.x * 64, 0, t * D_ + h * 64);
}
__global__ void trans_wo_kernel(const float* __restrict__ Wo) {
    trans_tile(Wo, D_, g_woh, g_wol, D_, blockIdx.x * 64, blockIdx.y * 64, 0);
}

// ------------------------ mma.sync bf16x3 GEMM (R12 exact) ------------------
#define GP_   5120                 // elements per part (128*40)
#define GSTG_ (4 * GP_)            // elements per stage
#define QSCALE_ 0.180336880f       // 0.125 * log2(e)
template <int MODE>
__global__ __launch_bounds__(256, 2)
void gemm_mma_kernel(const __nv_bfloat16* __restrict__ Ah,
                     const __nv_bfloat16* __restrict__ Al,
                     const __nv_bfloat16* __restrict__ Bh,
                     const __nv_bfloat16* __restrict__ Bl,
                     float* __restrict__ out, int ld_out,
                     const float* __restrict__ bias) {
    extern __shared__ __align__(16) char gsm[];
    const uint32_t sb = smem_u32(gsm);

    const int tid  = threadIdx.x;
    const int wid  = tid >> 5;
    const int lane = tid & 31;
    const int wr   = wid >> 2;
    const int wc   = wid & 3;
    const size_t m0 = blockIdx.y * 128;
    const size_t n0 = blockIdx.x * 128;

    const __nv_bfloat16* srcs[4] = {Ah, Al, Bh, Bl};
    const size_t rbase[4] = {m0, m0, n0, n0};

    auto load_st = [&](int kt, int st) {
        const int k0 = kt * 32;
#pragma unroll
        for (int it = 0; it < 8; it++) {
            int idx = tid + it * 256;
            int part = idx >> 9;
            int w = idx & 511;
            int row = w >> 2, c8 = w & 3;
            uint32_t dst = sb + (st * GSTG_ + part * GP_ + row * 40 + c8 * 8) * 2;
            const __nv_bfloat16* src =
                &srcs[part][(rbase[part] + row) * D_ + k0 + c8 * 8];
            CP_ASYNC16(dst, src);
        }
        CP_COMMIT();
    };

    float acc[4][4][4] = {};

    const int lrow = lane & 15;
    const int lcol = (lane >> 4) * 8;

    load_st(0, 0);

    for (int kt = 0; kt < 24; kt++) {
        const int st = kt & 1;
        if (kt < 23) { load_st(kt + 1, 1 - st); CP_WAIT(1); }
        else         { CP_WAIT(0); }
        __syncthreads();

        const uint32_t s0 = sb + (st * GSTG_) * 2;
#pragma unroll
        for (int ks = 0; ks < 2; ks++) {
            const int kb = ks * 16;
            const uint32_t arow = s0 + ((wr * 64 + lrow) * 40 + kb + lcol) * 2;
            const uint32_t brow = s0 + ((wc * 32 + lrow) * 40 + kb + lcol) * 2;

            uint32_t aF[4][4], bFh[2][4], bF2[2][4];
#pragma unroll
            for (int mt = 0; mt < 4; mt++)
                ldsm_x4(aF[mt], arow + (0 * GP_ + mt * 16 * 40) * 2);
#pragma unroll
            for (int np = 0; np < 2; np++)
                ldsm_x4(bFh[np], brow + (2 * GP_ + np * 16 * 40) * 2);
#pragma unroll
            for (int mt = 0; mt < 4; mt++)
#pragma unroll
                for (int nt = 0; nt < 4; nt++)
                    mma16816(acc[mt][nt], aF[mt], bFh[nt >> 1][nt & 1],
                             bFh[nt >> 1][(nt & 1) + 2]);
#pragma unroll
            for (int np = 0; np < 2; np++)
                ldsm_x4(bF2[np], brow + (3 * GP_ + np * 16 * 40) * 2);
#pragma unroll
            for (int mt = 0; mt < 4; mt++)
#pragma unroll
                for (int nt = 0; nt < 4; nt++)
                    mma16816(acc[mt][nt], aF[mt], bF2[nt >> 1][nt & 1],
                             bF2[nt >> 1][(nt & 1) + 2]);
#pragma unroll
            for (int mt = 0; mt < 4; mt++)
                ldsm_x4(aF[mt], arow + (1 * GP_ + mt * 16 * 40) * 2);
#pragma unroll
            for (int mt = 0; mt < 4; mt++)
#pragma unroll
                for (int nt = 0; nt < 4; nt++)
                    mma16816(acc[mt][nt], aF[mt], bFh[nt >> 1][nt & 1],
                             bFh[nt >> 1][(nt & 1) + 2]);
        }
        __syncthreads();
    }

    const int g = lane >> 2;
    const int cb = (lane & 3) * 2;

    if (MODE == 0) {
#pragma unroll
        for (int mt = 0; mt < 4; mt++)
#pragma unroll
            for (int nt = 0; nt < 4; nt++) {
                const size_t col = n0 + wc * 32 + nt * 8 + cb;
                float2 bv = *(const float2*)&bias[col];
                const size_t r0 = m0 + wr * 64 + mt * 16 + g;
                float2 v0 = {acc[mt][nt][0] + bv.x, acc[mt][nt][1] + bv.y};
                float2 v1 = {acc[mt][nt][2] + bv.x, acc[mt][nt][3] + bv.y};
                *(float2*)&out[r0 * ld_out + col]       = v0;
                *(float2*)&out[(r0 + 8) * ld_out + col] = v1;
            }
    } else {
        const int t  = (int)(n0 / D_);
        const int nn = (int)(n0 - t * D_);
        if (t < 2) {
            __nv_bfloat16* dh = (t == 0) ? g_qh : g_kh;
            __nv_bfloat16* dl = (t == 0) ? g_ql : g_kl;
            const float sc = (t == 0) ? QSCALE_ : 1.0f;
#pragma unroll
            for (int mt = 0; mt < 4; mt++)
#pragma unroll
                for (int nt = 0; nt < 4; nt++) {
                    const int colw = nn + wc * 32 + nt * 8 + cb;
                    float2 bv = *(const float2*)&bias[n0 + wc * 32 + nt * 8 + cb];
                    const size_t r0 = m0 + wr * 64 + mt * 16 + g;
                    uint32_t h0, l0, h1, l1;
                    split2((acc[mt][nt][0] + bv.x) * sc, (acc[mt][nt][1] + bv.y) * sc, h0, l0);
                    split2((acc[mt][nt][2] + bv.x) * sc, (acc[mt][nt][3] + bv.y) * sc, h1, l1);
                    *(uint32_t*)&dh[r0 * D_ + colw]       = h0;
                    *(uint32_t*)&dl[r0 * D_ + colw]       = l0;
                    *(uint32_t*)&dh[(r0 + 8) * D_ + colw] = h1;
                    *(uint32_t*)&dl[(r0 + 8) * D_ + colw] = l1;
                }
        } else {
            __nv_bfloat16* sm_h = (__nv_bfloat16*)gsm;
            __nv_bfloat16* sm_l = sm_h + 128 * 136;
#pragma unroll
            for (int mt = 0; mt < 4; mt++)
#pragma unroll
                for (int nt = 0; nt < 4; nt++) {
                    const int colw = wc * 32 + nt * 8 + cb;
                    float2 bv = *(const float2*)&bias[n0 + colw];
                    const int rl = wr * 64 + mt * 16 + g;
                    __nv_bfloat16 hh, ll;
                    split1(acc[mt][nt][0] + bv.x, hh, ll);
                    sm_h[colw * 136 + rl] = hh;       sm_l[colw * 136 + rl] = ll;
                    split1(acc[mt][nt][1] + bv.y, hh, ll);
                    sm_h[(colw + 1) * 136 + rl] = hh; sm_l[(colw + 1) * 136 + rl] = ll;
                    split1(acc[mt][nt][2] + bv.x, hh, ll);
                    sm_h[colw * 136 + rl + 8] = hh;       sm_l[colw * 136 + rl + 8] = ll;
                    split1(acc[mt][nt][3] + bv.y, hh, ll);
                    sm_h[(colw + 1) * 136 + rl + 8] = hh; sm_l[(colw + 1) * 136 + rl + 8] = ll;
                }
            __syncthreads();
            const int bidx  = (int)(m0 / S_);
            const int m0loc = (int)(m0 % S_);
#pragma unroll
            for (int it = 0; it < 8; it++) {
                int idx = tid + it * 256;
                int c = idx >> 4, sg = (idx & 15) * 8;
                int he = nn + c;
                int hh2 = he >> 6, e = he & 63;
                size_t ob = ((size_t)(bidx * H_ + hh2) * 64 + e) * S_ + m0loc + sg;
                *(uint4*)&g_vth[ob] = *(uint4*)&sm_h[c * 136 + sg];
                *(uint4*)&g_vtl[ob] = *(uint4*)&sm_l[c * 136 + sg];
            }
        }
    }
}

// ----------- mma.sync bf16x3 causal flash attention, pipelined --------------
// S(kt+1) MMAs issued before softmax(kt)+PV(kt) so MUFU/ALU softmax overlaps
// the tensor pipe. 4 KV buffers; ntiles is always even (2-tile unrolled loop).
#define PART_ 4608                 // elements per part (64*72)
#define BUF_  (4 * PART_)          // elements per KV buffer (18432)
__global__ __launch_bounds__(256, 1) void attn_mma_kernel() {
    extern __shared__ __align__(16) char dsm[];
    __nv_bfloat16* sm = (__nv_bfloat16*)dsm;
    const uint32_t sb = smem_u32(sm);

    const int tid = threadIdx.x, wid = tid >> 5, lane = tid & 31;
    const int qt = gridDim.x - 1 - blockIdx.x;
    const int bh = blockIdx.y;
    const int b = bh / H_, h = bh % H_;
    const int q0 = qt * 128;

    // ---- Q tile (pre-scaled by 0.125*log2e, pre-split) -> smem (buf0 area) --
#pragma unroll
    for (int it = 0; it < 8; it++) {
        int idx = tid + it * 256;
        int part = idx >> 10;
        int w = idx & 1023;
        int r = w >> 3, c8 = w & 7;
        const __nv_bfloat16* src = part ? g_ql : g_qh;
        *(uint4*)&sm[part * 9216 + r * 72 + c8 * 8] =
            *(const uint4*)&src[(size_t)(b * S_ + q0 + r) * D_ + h * 64 + c8 * 8];
    }
    __syncthreads();

    uint32_t aQh[4][4], aQl[4][4];
    {
        const int row = wid * 16 + (lane & 15);
        const int c8 = (lane >> 4) * 8;
#pragma unroll
        for (int kk = 0; kk < 4; kk++) {
            ldsm_x4(aQh[kk], sb + (row * 72 + kk * 16 + c8) * 2);
            ldsm_x4(aQl[kk], sb + (9216 + row * 72 + kk * 16 + c8) * 2);
        }
    }
    __syncthreads();   // Q area free; buffers may be written

    float oacc[8][4] = {};
    float mrun[2] = {-1e30f, -1e30f}, lrun[2] = {0.0f, 0.0f};

    const int lrw = lane & 15;
    const int cb8 = (lane >> 4) * 8;
    const int ntiles = 2 * qt + 2;     // always even
    const int mask_from = 2 * qt;

    auto load_tile = [&](int kt, int bs) {
        const int k0 = kt * 64;
#pragma unroll
        for (int it = 0; it < 8; it++) {
            int idx = tid + it * 256;
            int part = idx >> 9;
            int w = idx & 511;
            int row = w >> 3, c8 = w & 7;
            uint32_t dst = sb + (bs * BUF_ + part * PART_ + row * 72 + c8 * 8) * 2;
            const __nv_bfloat16* src;
            if (part < 2) {
                const __nv_bfloat16* base = part ? g_kl : g_kh;
                src = &base[(size_t)(b * S_ + k0 + row) * D_ + h * 64 + c8 * 8];
            } else {
                const __nv_bfloat16* base = (part == 2) ? g_vth : g_vtl;
                src = &base[((size_t)bh * 64 + row) * S_ + k0 + c8 * 8];
            }
            CP_ASYNC16(dst, src);
        }
        CP_COMMIT();
    };

    // S = Q K^T for tile kt into sacc
    auto s_compute = [&](float (&sacc)[8][4], int kt) {
        const uint32_t kbase = sb + ((kt & 3) * BUF_) * 2;
#pragma unroll
        for (int nt = 0; nt < 8; nt++)
#pragma unroll
            for (int e = 0; e < 4; e++) sacc[nt][e] = 0.0f;
#pragma unroll
        for (int kk = 0; kk < 4; kk++) {
#pragma unroll
            for (int np = 0; np < 4; np++) {
                uint32_t kbh[4], kbl[4];
                ldsm_x4(kbh, kbase + ((np * 16 + lrw) * 72 + kk * 16 + cb8) * 2);
                ldsm_x4(kbl, kbase + (PART_ + (np * 16 + lrw) * 72 + kk * 16 + cb8) * 2);
#pragma unroll
                for (int ni = 0; ni < 2; ni++) {
                    const int nt = np * 2 + ni;
                    mma16816(sacc[nt], aQh[kk], kbh[ni], kbh[ni + 2]);
                    mma16816(sacc[nt], aQh[kk], kbl[ni], kbl[ni + 2]);
                    mma16816(sacc[nt], aQl[kk], kbh[ni], kbh[ni + 2]);
                }
            }
        }
    };

    // mask + streaming softmax (base 2) + P repack + PV for tile kt
    auto softmax_pv = [&](float (&sacc)[8][4], int kt) {
        const int k0 = kt * 64;
        if (kt >= mask_from) {
#pragma unroll
            for (int nt = 0; nt < 8; nt++)
#pragma unroll
                for (int e = 0; e < 4; e++) {
                    const int row = q0 + wid * 16 + (lane >> 2) + (e >> 1) * 8;
                    const int col = k0 + nt * 8 + (lane & 3) * 2 + (e & 1);
                    if (col > row) sacc[nt][e] = -1e30f;
                }
        }
#pragma unroll
        for (int rg = 0; rg < 2; rg++) {
            float mloc = -1e30f;
#pragma unroll
            for (int nt = 0; nt < 8; nt++)
                mloc = fmaxf(mloc, fmaxf(sacc[nt][rg * 2], sacc[nt][rg * 2 + 1]));
            mloc = fmaxf(mloc, __shfl_xor_sync(0xffffffffu, mloc, 1));
            mloc = fmaxf(mloc, __shfl_xor_sync(0xffffffffu, mloc, 2));
            const float mnew = fmaxf(mrun[rg], mloc);
            const float alpha = ex2f(mrun[rg] - mnew);
            float lloc = 0.0f;
#pragma unroll
            for (int nt = 0; nt < 8; nt++) {
                sacc[nt][rg * 2]     = ex2f(sacc[nt][rg * 2] - mnew);
                sacc[nt][rg * 2 + 1] = ex2f(sacc[nt][rg * 2 + 1] - mnew);
                lloc += sacc[nt][rg * 2] + sacc[nt][rg * 2 + 1];
            }
            lloc += __shfl_xor_sync(0xffffffffu, lloc, 1);
            lloc += __shfl_xor_sync(0xffffffffu, lloc, 2);
            lrun[rg] = lrun[rg] * alpha + lloc;
            mrun[rg] = mnew;
#pragma unroll
            for (int dt = 0; dt < 8; dt++) {
                oacc[dt][rg * 2]     *= alpha;
                oacc[dt][rg * 2 + 1] *= alpha;
            }
        }

        uint32_t aPh[4][4], aPl[4][4];
#pragma unroll
        for (int k2 = 0; k2 < 4; k2++) {
            split2(sacc[k2 * 2][0],     sacc[k2 * 2][1],     aPh[k2][0], aPl[k2][0]);
            split2(sacc[k2 * 2][2],     sacc[k2 * 2][3],     aPh[k2][1], aPl[k2][1]);
            split2(sacc[k2 * 2 + 1][0], sacc[k2 * 2 + 1][1], aPh[k2][2], aPl[k2][2]);
            split2(sacc[k2 * 2 + 1][2], sacc[k2 * 2 + 1][3], aPh[k2][3], aPl[k2][3]);
        }

        const uint32_t vbase = sb + ((kt & 3) * BUF_ + 2 * PART_) * 2;
#pragma unroll
        for (int k2 = 0; k2 < 4; k2++) {
#pragma unroll
            for (int dp = 0; dp < 4; dp++) {
                uint32_t vbh[4], vbl[4];
                ldsm_x4(vbh, vbase + ((dp * 16 + lrw) * 72 + k2 * 16 + cb8) * 2);
                ldsm_x4(vbl, vbase + (PART_ + (dp * 16 + lrw) * 72 + k2 * 16 + cb8) * 2);
#pragma unroll
                for (int ni = 0; ni < 2; ni++) {
                    const int dt = dp * 2 + ni;
                    mma16816(oacc[dt], aPh[k2], vbh[ni], vbh[ni + 2]);
                    mma16816(oacc[dt], aPh[k2], vbl[ni], vbl[ni + 2]);
                    mma16816(oacc[dt], aPl[k2], vbh[ni], vbh[ni + 2]);
                }
            }
        }
    };

    load_tile(0, 0);
    load_tile(1, 1);

    float sA[8][4], sB[8][4];

    for (int kt2 = 0; kt2 < ntiles; kt2 += 2) {
        // ---- sub-iter for tile kt2 ----
        CP_WAIT(1);                         // load(kt2) complete
        __syncthreads();                    // data visible; buf (kt2+2)&3 free
        if (kt2 + 2 < ntiles) load_tile(kt2 + 2, (kt2 + 2) & 3);
        s_compute(sA, kt2);                 // tensor pipe busy...
        if (kt2 > 0) softmax_pv(sB, kt2 - 1);   // ...while MUFU/ALU run

        // ---- sub-iter for tile kt2+1 ----
        if (kt2 + 2 < ntiles) CP_WAIT(1); else CP_WAIT(0);  // load(kt2+1) done
        __syncthreads();
        if (kt2 + 3 < ntiles) load_tile(kt2 + 3, (kt2 + 3) & 3);
        s_compute(sB, kt2 + 1);
        softmax_pv(sA, kt2);
    }
    softmax_pv(sB, ntiles - 1);

    // ---- epilogue: z = O / l, split bf16 hi/lo ----
#pragma unroll
    for (int rg = 0; rg < 2; rg++) {
        const float inv = 1.0f / lrun[rg];
        const int row = q0 + wid * 16 + (lane >> 2) + rg * 8;
#pragma unroll
        for (int dt = 0; dt < 8; dt++) {
            const size_t o = (size_t)(b * S_ + row) * D_ + h * 64 + dt * 8 + (lane & 3) * 2;
            uint32_t hp, lp;
            split2(oacc[dt][rg * 2] * inv, oacc[dt][rg * 2 + 1] * inv, hp, lp);
            *(uint32_t*)&g_zh[o] = hp;
            *(uint32_t*)&g_zl[o] = lp;
        }
    }
}

// --------------------------------- launch ----------------------------------
extern "C" void kernel_launch(void* const* d_in, const int* in_sizes, int n_in,
                              void* d_out, int out_size) {
    const float* X  = (const float*)d_in[0];
    const float* Wq = (const float*)d_in[1];
    const float* Wk = (const float*)d_in[2];
    const float* Wv = (const float*)d_in[3];
    const float* Wo = (const float*)d_in[4];
    const float* bq = (const float*)d_in[5];
    const float* bk = (const float*)d_in[6];
    const float* bv = (const float*)d_in[7];
    const float* bo = (const float*)d_in[8];
    float* out = (float*)d_out;

    const int attn_smem = 4 * BUF_ * 2;     // 147456 B
    const int gemm_smem = 2 * GSTG_ * 2;    // 81920 B
    static bool attr_set = false;
    if (!attr_set) {
        cudaFuncSetAttribute(attn_mma_kernel,
                             cudaFuncAttributeMaxDynamicSharedMemorySize, attn_smem);
        cudaFuncSetAttribute(gemm_mma_kernel<0>,
                             cudaFuncAttributeMaxDynamicSharedMemorySize, gemm_smem);
        cudaFuncSetAttribute(gemm_mma_kernel<1>,
                             cudaFuncAttributeMaxDynamicSharedMemorySize, gemm_smem);
        attr_set = true;
    }

    static __nv_bfloat16 *xh = nullptr, *xl, *zh, *zl, *wth, *wtl, *woh, *wol;
    static float *fb;
    if (!xh) {
        cudaGetSymbolAddress((void**)&xh,  g_xh);
        cudaGetSymbolAddress((void**)&xl,  g_xl);
        cudaGetSymbolAddress((void**)&zh,  g_zh);
        cudaGetSymbolAddress((void**)&zl,  g_zl);
        cudaGetSymbolAddress((void**)&wth, g_wth);
        cudaGetSymbolAddress((void**)&wtl, g_wtl);
        cudaGetSymbolAddress((void**)&woh, g_woh);
        cudaGetSymbolAddress((void**)&wol, g_wol);
        cudaGetSymbolAddress((void**)&fb,  g_fb);
    }

    // 1) conversions
    split_kernel<<<(M_ * D_) / (256 * 8), 256>>>(X, xh, xl, M_ * D_);
    trans_qkv_kernel<<<dim3(D_ / 64, 3 * H_), 256>>>(Wq, Wk, Wv, bq, bk, bv);
    trans_wo_kernel<<<dim3(D_ / 64, D_ / 64), 256>>>(Wo);

    // 2) fused QKV projection -> q/k split bf16 + V transposed split bf16
    gemm_mma_kernel<1><<<dim3(NF_ / 128, M_ / 128), 256, gemm_smem>>>(
        xh, xl, wth, wtl, nullptr, 0, fb);

    // 3) causal attention (pipelined softmax/MMA overlap)
    attn_mma_kernel<<<dim3(S_ / 128, B_ * H_), 256, attn_smem>>>();

    // 4) output projection
    gemm_mma_kernel<0><<<dim3(D_ / 128, M_ / 128), 256, gemm_smem>>>(
        zh, zl, woh, wol, out, D_, bo);
}